// round 1
// baseline (speedup 1.0000x reference)
#include <cuda_runtime.h>
#include <math.h>

#define SEQ 2048
#define BATCH 2
#define HIDDEN 4096
#define HD 128
#define HQ 32
#define HKV 8
#define WINDOW 1024
#define NEG_INF_F (-1e30f)

// ---------------- scratch (static device arrays; no allocations) ----------------
__device__ float g_xn[(size_t)BATCH * SEQ * HIDDEN];    // 64 MB
__device__ float g_q[(size_t)BATCH * SEQ * HQ * HD];    // 64 MB
__device__ float g_k[(size_t)BATCH * SEQ * HKV * HD];   // 16 MB
__device__ float g_v[(size_t)BATCH * SEQ * HKV * HD];   // 16 MB
__device__ float g_attn[(size_t)BATCH * SEQ * HQ * HD]; // 64 MB
__device__ float g_cos[SEQ * (HD / 2)];
__device__ float g_sin[SEQ * (HD / 2)];

// ---------------- RMSNorm ----------------
__global__ __launch_bounds__(256) void rmsnorm_kernel(
    const float* __restrict__ x, const float* __restrict__ gamma,
    float* __restrict__ xn) {
    const int row = blockIdx.x;
    const float4* xr = (const float4*)(x + (size_t)row * HIDDEN);
    const float4* g4 = (const float4*)gamma;
    float4* o4 = (float4*)(xn + (size_t)row * HIDDEN);

    float ss = 0.f;
    float4 v[4];
#pragma unroll
    for (int i = 0; i < 4; i++) {
        v[i] = xr[threadIdx.x + 256 * i];
        ss += v[i].x * v[i].x + v[i].y * v[i].y + v[i].z * v[i].z + v[i].w * v[i].w;
    }
#pragma unroll
    for (int o = 16; o > 0; o >>= 1) ss += __shfl_xor_sync(~0u, ss, o);

    __shared__ float sred[8];
    if ((threadIdx.x & 31) == 0) sred[threadIdx.x >> 5] = ss;
    __syncthreads();
    float tot = 0.f;
#pragma unroll
    for (int i = 0; i < 8; i++) tot += sred[i];

    const float inv = rsqrtf(tot / (float)HIDDEN + 1e-5f);
#pragma unroll
    for (int i = 0; i < 4; i++) {
        float4 g = g4[threadIdx.x + 256 * i];
        float4 o;
        o.x = v[i].x * inv * g.x;
        o.y = v[i].y * inv * g.y;
        o.z = v[i].z * inv * g.z;
        o.w = v[i].w * inv * g.w;
        o4[threadIdx.x + 256 * i] = o;
    }
}

// ---------------- RoPE tables (double precision, tiny kernel) ----------------
__global__ void rope_table_kernel(float* __restrict__ cosT, float* __restrict__ sinT) {
    int idx = blockIdx.x * blockDim.x + threadIdx.x;
    if (idx >= SEQ * 64) return;
    int s = idx >> 6, i = idx & 63;
    double ang = (double)s * pow(10000.0, -(double)i / 64.0);
    double sn, cs;
    sincos(ang, &sn, &cs);
    cosT[idx] = (float)cs;
    sinT[idx] = (float)sn;
}

// ---------------- RoPE apply (in place) ----------------
__global__ __launch_bounds__(256) void rope_apply_kernel(
    float* __restrict__ t, int nheads, long total) {
    long idx = (long)blockIdx.x * blockDim.x + threadIdx.x;
    if (idx >= total) return;
    int i = (int)(idx & 63);
    long vi = idx >> 6;
    int s = (int)((vi / nheads) % SEQ);
    float c = g_cos[s * 64 + i];
    float sn = g_sin[s * 64 + i];
    float* p = t + vi * HD;
    float a = p[i], b = p[i + 64];
    p[i] = a * c - b * sn;
    p[i + 64] = b * c + a * sn;
}

// ---------------- fp32 tiled GEMM: C = A(MxK) @ B(KxN) [+ R] ----------------
#define BM 128
#define BN 128
#define BK 16
__global__ __launch_bounds__(256) void gemm_kernel(
    const float* __restrict__ A, const float* __restrict__ B,
    const float* __restrict__ R, float* __restrict__ C,
    int M, int N, int K) {
    __shared__ float As[BK][BM + 4];
    __shared__ float Bs[BK][BN];

    const int tid = threadIdx.x;
    const int tx = tid & 15, ty = tid >> 4;
    const int row0 = blockIdx.y * BM, col0 = blockIdx.x * BN;

    float acc[8][8] = {};
    const int aRow = tid >> 2, aCol = (tid & 3) << 2;   // A: 64 rows x 16 cols per pass
    const int bRow = tid >> 5, bCol = (tid & 31) << 2;  // B: 8 rows x 128 cols per pass

    for (int k0 = 0; k0 < K; k0 += BK) {
#pragma unroll
        for (int i = 0; i < BM; i += 64) {
            float4 va = *(const float4*)&A[(size_t)(row0 + aRow + i) * K + k0 + aCol];
            As[aCol + 0][aRow + i] = va.x;
            As[aCol + 1][aRow + i] = va.y;
            As[aCol + 2][aRow + i] = va.z;
            As[aCol + 3][aRow + i] = va.w;
        }
#pragma unroll
        for (int i = 0; i < BK; i += 8) {
            *(float4*)&Bs[bRow + i][bCol] =
                *(const float4*)&B[(size_t)(k0 + bRow + i) * N + col0 + bCol];
        }
        __syncthreads();

#pragma unroll
        for (int kk = 0; kk < BK; kk++) {
            float ar[8], br[8];
            *(float4*)&ar[0] = *(float4*)&As[kk][ty * 8];
            *(float4*)&ar[4] = *(float4*)&As[kk][ty * 8 + 4];
            *(float4*)&br[0] = *(float4*)&Bs[kk][tx * 8];
            *(float4*)&br[4] = *(float4*)&Bs[kk][tx * 8 + 4];
#pragma unroll
            for (int i = 0; i < 8; i++)
#pragma unroll
                for (int j = 0; j < 8; j++) acc[i][j] += ar[i] * br[j];
        }
        __syncthreads();
    }

#pragma unroll
    for (int i = 0; i < 8; i++) {
        size_t r = row0 + ty * 8 + i;
#pragma unroll
        for (int j = 0; j < 8; j += 4) {
            size_t c = col0 + tx * 8 + j;
            float4 v = make_float4(acc[i][j], acc[i][j + 1], acc[i][j + 2], acc[i][j + 3]);
            if (R) {
                float4 rv = *(const float4*)&R[r * N + c];
                v.x += rv.x; v.y += rv.y; v.z += rv.z; v.w += rv.w;
            }
            *(float4*)&C[r * N + c] = v;
        }
    }
}

// ---------------- flash attention (windowed causal + tanh cap) ----------------
// grid: (S/64, HQ, B), 256 threads.
// smem: sQ 64x128 | sK 64x132(pad) | sV 64x128 | sS 64x68(pad)
#define ATT_SMEM ((64 * 128 + 64 * 132 + 64 * 128 + 64 * 68) * 4)
__global__ __launch_bounds__(256) void attn_kernel(
    const float* __restrict__ Q, const float* __restrict__ K,
    const float* __restrict__ V, float* __restrict__ O) {
    extern __shared__ float sm[];
    float* sQ = sm;               // 64*128
    float* sK = sQ + 64 * 128;    // 64*132
    float* sV = sK + 64 * 132;    // 64*128
    float* sS = sV + 64 * 128;    // 64*68

    const int qt = blockIdx.x, h = blockIdx.y, b = blockIdx.z;
    const int g = h >> 2;  // n_rep = HQ/HKV = 4
    const int q0 = qt * 64;
    const int tid = threadIdx.x;
    const int tx = tid & 15, ty = tid >> 4;       // phase-1: 16x16 threads, 4x4 tile each
    const int myrow = tid >> 2, dq = tid & 3;     // phase-2/3: 4 threads per query row
    const int dim0 = dq * 32;

    // load Q tile (64 rows x 128 dims), coalesced float4
    for (int i = tid; i < 64 * 32; i += 256) {
        int r = i >> 5, c = (i & 31) << 2;
        *(float4*)&sQ[r * 128 + c] =
            *(const float4*)&Q[(((size_t)b * SEQ + q0 + r) * HQ + h) * HD + c];
    }

    float acc[32];
#pragma unroll
    for (int i = 0; i < 32; i++) acc[i] = 0.f;
    float m_run = NEG_INF_F, l_run = 0.f;

    const int kt_lo = max(0, q0 - WINDOW + 1) >> 6;
    const float scale = 0.08838834764831845f;  // 1/sqrt(128)
    const float invcap = 1.0f / 50.0f;

    for (int kt = kt_lo; kt <= qt; kt++) {
        const int k0 = kt * 64;
        __syncthreads();  // protect smem reuse from previous iteration
        for (int i = tid; i < 64 * 32; i += 256) {
            int r = i >> 5, c = (i & 31) << 2;
            size_t base = (((size_t)b * SEQ + k0 + r) * HKV + g) * HD + c;
            *(float4*)&sK[r * 132 + c] = *(const float4*)&K[base];
            *(float4*)&sV[r * 128 + c] = *(const float4*)&V[base];
        }
        __syncthreads();

        // ---- phase 1: scores S = Q K^T (4x4 per thread) ----
        float sc[4][4];
#pragma unroll
        for (int i = 0; i < 4; i++)
#pragma unroll
            for (int j = 0; j < 4; j++) sc[i][j] = 0.f;

#pragma unroll 4
        for (int d4 = 0; d4 < 32; d4++) {
            float4 qv[4], kv[4];
#pragma unroll
            for (int i = 0; i < 4; i++) qv[i] = *(float4*)&sQ[(ty * 4 + i) * 128 + d4 * 4];
#pragma unroll
            for (int j = 0; j < 4; j++) kv[j] = *(float4*)&sK[(tx * 4 + j) * 132 + d4 * 4];
#pragma unroll
            for (int i = 0; i < 4; i++)
#pragma unroll
                for (int j = 0; j < 4; j++)
                    sc[i][j] += qv[i].x * kv[j].x + qv[i].y * kv[j].y +
                                qv[i].z * kv[j].z + qv[i].w * kv[j].w;
        }

#pragma unroll
        for (int i = 0; i < 4; i++) {
            int gi = q0 + ty * 4 + i;
#pragma unroll
            for (int j = 0; j < 4; j++) {
                int gj = k0 + tx * 4 + j;
                float s_v = 50.0f * tanhf(sc[i][j] * scale * invcap);
                bool valid = (gj <= gi) && (gj > gi - WINDOW);
                sS[(ty * 4 + i) * 68 + tx * 4 + j] = valid ? s_v : NEG_INF_F;
            }
        }
        __syncthreads();

        // ---- phase 2: online softmax (4 threads per row, 16 cols each) ----
        float svals[16];
        float tmax = NEG_INF_F;
#pragma unroll
        for (int j = 0; j < 16; j++) {
            svals[j] = sS[myrow * 68 + dq * 16 + j];
            tmax = fmaxf(tmax, svals[j]);
        }
        tmax = fmaxf(tmax, __shfl_xor_sync(~0u, tmax, 1));
        tmax = fmaxf(tmax, __shfl_xor_sync(~0u, tmax, 2));
        float m_new = fmaxf(m_run, tmax);
        float corr = expf(m_run - m_new);  // 0 if m_run=-inf & m_new finite; 1 if both -inf
        float psum = 0.f;
#pragma unroll
        for (int j = 0; j < 16; j++) {
            // guard: masked entries must give exactly 0 even when m_new is still -1e30
            float p = (svals[j] > -1e29f) ? expf(svals[j] - m_new) : 0.f;
            sS[myrow * 68 + dq * 16 + j] = p;
            psum += p;
        }
        psum += __shfl_xor_sync(~0u, psum, 1);
        psum += __shfl_xor_sync(~0u, psum, 2);
        l_run = l_run * corr + psum;
        m_run = m_new;
        __syncwarp();  // p-values for my row were written by my own quad (same warp)

        // ---- phase 3: O += P @ V (thread owns row `myrow`, dims [dim0, dim0+32)) ----
#pragma unroll
        for (int i = 0; i < 32; i++) acc[i] *= corr;
        for (int t = 0; t < 64; t++) {
            float p = sS[myrow * 68 + t];
#pragma unroll
            for (int i = 0; i < 32; i += 4) {
                float4 vv = *(float4*)&sV[t * 128 + dim0 + i];
                acc[i] += p * vv.x;
                acc[i + 1] += p * vv.y;
                acc[i + 2] += p * vv.z;
                acc[i + 3] += p * vv.w;
            }
        }
    }

    const float invl = 1.f / l_run;
    size_t orow = ((size_t)b * SEQ + q0 + myrow) * (size_t)(HQ * HD) + (size_t)h * HD + dim0;
#pragma unroll
    for (int i = 0; i < 32; i += 4) {
        float4 v = make_float4(acc[i] * invl, acc[i + 1] * invl,
                               acc[i + 2] * invl, acc[i + 3] * invl);
        *(float4*)&O[orow + i] = v;
    }
}

// ---------------- launch ----------------
extern "C" void kernel_launch(void* const* d_in, const int* in_sizes, int n_in,
                              void* d_out, int out_size) {
    const float* x = (const float*)d_in[0];
    const float* gamma = (const float*)d_in[1];
    const float* Wq = (const float*)d_in[2];
    const float* Wk = (const float*)d_in[3];
    const float* Wv = (const float*)d_in[4];
    const float* Wo = (const float*)d_in[5];
    float* out = (float*)d_out;

    float *xn, *q, *k, *v, *attn, *cosT, *sinT;
    cudaGetSymbolAddress((void**)&xn, g_xn);
    cudaGetSymbolAddress((void**)&q, g_q);
    cudaGetSymbolAddress((void**)&k, g_k);
    cudaGetSymbolAddress((void**)&v, g_v);
    cudaGetSymbolAddress((void**)&attn, g_attn);
    cudaGetSymbolAddress((void**)&cosT, g_cos);
    cudaGetSymbolAddress((void**)&sinT, g_sin);

    cudaFuncSetAttribute(attn_kernel, cudaFuncAttributeMaxDynamicSharedMemorySize, ATT_SMEM);

    const int M = BATCH * SEQ;  // 4096

    // 1) RMSNorm
    rmsnorm_kernel<<<M, 256>>>(x, gamma, xn);

    // 2) RoPE tables
    rope_table_kernel<<<(SEQ * 64 + 255) / 256, 256>>>(cosT, sinT);

    // 3) QKV projections
    {
        dim3 gq(HQ * HD / BN, M / BM);
        gemm_kernel<<<gq, 256>>>(xn, Wq, nullptr, q, M, HQ * HD, HIDDEN);
        dim3 gk(HKV * HD / BN, M / BM);
        gemm_kernel<<<gk, 256>>>(xn, Wk, nullptr, k, M, HKV * HD, HIDDEN);
        gemm_kernel<<<gk, 256>>>(xn, Wv, nullptr, v, M, HKV * HD, HIDDEN);
    }

    // 4) RoPE apply (in place)
    {
        long tq = (long)M * HQ * 64;
        rope_apply_kernel<<<(int)((tq + 255) / 256), 256>>>(q, HQ, tq);
        long tk = (long)M * HKV * 64;
        rope_apply_kernel<<<(int)((tk + 255) / 256), 256>>>(k, HKV, tk);
    }

    // 5) attention
    {
        dim3 ga(SEQ / 64, HQ, BATCH);
        attn_kernel<<<ga, 256, ATT_SMEM>>>(q, k, v, attn);
    }

    // 6) output projection + residual
    {
        dim3 go(HIDDEN / BN, M / BM);
        gemm_kernel<<<go, 256>>>(attn, Wo, x, out, M, HIDDEN, HIDDEN);
    }
}

// round 2
// speedup vs baseline: 1.0005x; 1.0005x over previous
#include <cuda_runtime.h>
#include <math.h>

#define SEQ 2048
#define BATCH 2
#define HIDDEN 4096
#define HD 128
#define HQ 32
#define HKV 8
#define WINDOW 1024
#define NEG_INF_F (-1e30f)

// ---------------- scratch (static device arrays; no allocations) ----------------
__device__ float g_xn[(size_t)BATCH * SEQ * HIDDEN];    // 64 MB
__device__ float g_q[(size_t)BATCH * SEQ * HQ * HD];    // 64 MB
__device__ float g_k[(size_t)BATCH * SEQ * HKV * HD];   // 16 MB
__device__ float g_v[(size_t)BATCH * SEQ * HKV * HD];   // 16 MB
__device__ float g_attn[(size_t)BATCH * SEQ * HQ * HD]; // 64 MB
__device__ float g_cos[SEQ * (HD / 2)];
__device__ float g_sin[SEQ * (HD / 2)];

// ---------------- RMSNorm ----------------
__global__ __launch_bounds__(256) void rmsnorm_kernel(
    const float* __restrict__ x, const float* __restrict__ gamma,
    float* __restrict__ xn) {
    const int row = blockIdx.x;
    const float4* xr = (const float4*)(x + (size_t)row * HIDDEN);
    const float4* g4 = (const float4*)gamma;
    float4* o4 = (float4*)(xn + (size_t)row * HIDDEN);

    float ss = 0.f;
    float4 v[4];
#pragma unroll
    for (int i = 0; i < 4; i++) {
        v[i] = xr[threadIdx.x + 256 * i];
        ss += v[i].x * v[i].x + v[i].y * v[i].y + v[i].z * v[i].z + v[i].w * v[i].w;
    }
#pragma unroll
    for (int o = 16; o > 0; o >>= 1) ss += __shfl_xor_sync(~0u, ss, o);

    __shared__ float sred[8];
    if ((threadIdx.x & 31) == 0) sred[threadIdx.x >> 5] = ss;
    __syncthreads();
    float tot = 0.f;
#pragma unroll
    for (int i = 0; i < 8; i++) tot += sred[i];

    const float inv = rsqrtf(tot / (float)HIDDEN + 1e-5f);
#pragma unroll
    for (int i = 0; i < 4; i++) {
        float4 g = g4[threadIdx.x + 256 * i];
        float4 o;
        o.x = v[i].x * inv * g.x;
        o.y = v[i].y * inv * g.y;
        o.z = v[i].z * inv * g.z;
        o.w = v[i].w * inv * g.w;
        o4[threadIdx.x + 256 * i] = o;
    }
}

// ---------------- RoPE tables (double precision, tiny kernel) ----------------
__global__ void rope_table_kernel(float* __restrict__ cosT, float* __restrict__ sinT) {
    int idx = blockIdx.x * blockDim.x + threadIdx.x;
    if (idx >= SEQ * 64) return;
    int s = idx >> 6, i = idx & 63;
    double ang = (double)s * pow(10000.0, -(double)i / 64.0);
    double sn, cs;
    sincos(ang, &sn, &cs);
    cosT[idx] = (float)cs;
    sinT[idx] = (float)sn;
}

// ---------------- RoPE apply (in place) ----------------
__global__ __launch_bounds__(256) void rope_apply_kernel(
    float* __restrict__ t, int nheads, long total) {
    long idx = (long)blockIdx.x * blockDim.x + threadIdx.x;
    if (idx >= total) return;
    int i = (int)(idx & 63);
    long vi = idx >> 6;
    int s = (int)((vi / nheads) % SEQ);
    float c = g_cos[s * 64 + i];
    float sn = g_sin[s * 64 + i];
    float* p = t + vi * HD;
    float a = p[i], b = p[i + 64];
    p[i] = a * c - b * sn;
    p[i + 64] = b * c + a * sn;
}

// ---------------- fp32 tiled GEMM: C = A(MxK) @ B(KxN) [+ R] ----------------
#define BM 128
#define BN 128
#define BK 16
__global__ __launch_bounds__(256) void gemm_kernel(
    const float* __restrict__ A, const float* __restrict__ B,
    const float* __restrict__ R, float* __restrict__ C,
    int M, int N, int K) {
    __shared__ float As[BK][BM + 4];
    __shared__ float Bs[BK][BN];

    const int tid = threadIdx.x;
    const int tx = tid & 15, ty = tid >> 4;
    const int row0 = blockIdx.y * BM, col0 = blockIdx.x * BN;

    float acc[8][8] = {};
    const int aRow = tid >> 2, aCol = (tid & 3) << 2;   // A: 64 rows x 16 cols per pass
    const int bRow = tid >> 5, bCol = (tid & 31) << 2;  // B: 8 rows x 128 cols per pass

    for (int k0 = 0; k0 < K; k0 += BK) {
#pragma unroll
        for (int i = 0; i < BM; i += 64) {
            float4 va = *(const float4*)&A[(size_t)(row0 + aRow + i) * K + k0 + aCol];
            As[aCol + 0][aRow + i] = va.x;
            As[aCol + 1][aRow + i] = va.y;
            As[aCol + 2][aRow + i] = va.z;
            As[aCol + 3][aRow + i] = va.w;
        }
#pragma unroll
        for (int i = 0; i < BK; i += 8) {
            *(float4*)&Bs[bRow + i][bCol] =
                *(const float4*)&B[(size_t)(k0 + bRow + i) * N + col0 + bCol];
        }
        __syncthreads();

#pragma unroll
        for (int kk = 0; kk < BK; kk++) {
            float ar[8], br[8];
            *(float4*)&ar[0] = *(float4*)&As[kk][ty * 8];
            *(float4*)&ar[4] = *(float4*)&As[kk][ty * 8 + 4];
            *(float4*)&br[0] = *(float4*)&Bs[kk][tx * 8];
            *(float4*)&br[4] = *(float4*)&Bs[kk][tx * 8 + 4];
#pragma unroll
            for (int i = 0; i < 8; i++)
#pragma unroll
                for (int j = 0; j < 8; j++) acc[i][j] += ar[i] * br[j];
        }
        __syncthreads();
    }

#pragma unroll
    for (int i = 0; i < 8; i++) {
        size_t r = row0 + ty * 8 + i;
#pragma unroll
        for (int j = 0; j < 8; j += 4) {
            size_t c = col0 + tx * 8 + j;
            float4 v = make_float4(acc[i][j], acc[i][j + 1], acc[i][j + 2], acc[i][j + 3]);
            if (R) {
                float4 rv = *(const float4*)&R[r * N + c];
                v.x += rv.x; v.y += rv.y; v.z += rv.z; v.w += rv.w;
            }
            *(float4*)&C[r * N + c] = v;
        }
    }
}

// ---------------- flash attention (windowed causal + tanh cap) ----------------
// grid: (S/64, HQ, B), 256 threads.
// smem: sQ 64x128 | sK 64x132(pad) | sV 64x128 | sS 64x68(pad)
#define ATT_SMEM ((64 * 128 + 64 * 132 + 64 * 128 + 64 * 68) * 4)
__global__ __launch_bounds__(256) void attn_kernel(
    const float* __restrict__ Q, const float* __restrict__ K,
    const float* __restrict__ V, float* __restrict__ O) {
    extern __shared__ float sm[];
    float* sQ = sm;               // 64*128
    float* sK = sQ + 64 * 128;    // 64*132
    float* sV = sK + 64 * 132;    // 64*128
    float* sS = sV + 64 * 128;    // 64*68

    const int qt = blockIdx.x, h = blockIdx.y, b = blockIdx.z;
    const int g = h >> 2;  // n_rep = HQ/HKV = 4
    const int q0 = qt * 64;
    const int tid = threadIdx.x;
    const int tx = tid & 15, ty = tid >> 4;       // phase-1: 16x16 threads, 4x4 tile each
    const int myrow = tid >> 2, dq = tid & 3;     // phase-2/3: 4 threads per query row
    const int dim0 = dq * 32;

    // load Q tile (64 rows x 128 dims), coalesced float4
    for (int i = tid; i < 64 * 32; i += 256) {
        int r = i >> 5, c = (i & 31) << 2;
        *(float4*)&sQ[r * 128 + c] =
            *(const float4*)&Q[(((size_t)b * SEQ + q0 + r) * HQ + h) * HD + c];
    }

    float acc[32];
#pragma unroll
    for (int i = 0; i < 32; i++) acc[i] = 0.f;
    float m_run = NEG_INF_F, l_run = 0.f;

    const int kt_lo = max(0, q0 - WINDOW + 1) >> 6;
    const float scale = 0.08838834764831845f;  // 1/sqrt(128)
    const float invcap = 1.0f / 50.0f;

    for (int kt = kt_lo; kt <= qt; kt++) {
        const int k0 = kt * 64;
        __syncthreads();  // protect smem reuse from previous iteration
        for (int i = tid; i < 64 * 32; i += 256) {
            int r = i >> 5, c = (i & 31) << 2;
            size_t base = (((size_t)b * SEQ + k0 + r) * HKV + g) * HD + c;
            *(float4*)&sK[r * 132 + c] = *(const float4*)&K[base];
            *(float4*)&sV[r * 128 + c] = *(const float4*)&V[base];
        }
        __syncthreads();

        // ---- phase 1: scores S = Q K^T (4x4 per thread) ----
        float sc[4][4];
#pragma unroll
        for (int i = 0; i < 4; i++)
#pragma unroll
            for (int j = 0; j < 4; j++) sc[i][j] = 0.f;

#pragma unroll 4
        for (int d4 = 0; d4 < 32; d4++) {
            float4 qv[4], kv[4];
#pragma unroll
            for (int i = 0; i < 4; i++) qv[i] = *(float4*)&sQ[(ty * 4 + i) * 128 + d4 * 4];
#pragma unroll
            for (int j = 0; j < 4; j++) kv[j] = *(float4*)&sK[(tx * 4 + j) * 132 + d4 * 4];
#pragma unroll
            for (int i = 0; i < 4; i++)
#pragma unroll
                for (int j = 0; j < 4; j++)
                    sc[i][j] += qv[i].x * kv[j].x + qv[i].y * kv[j].y +
                                qv[i].z * kv[j].z + qv[i].w * kv[j].w;
        }

#pragma unroll
        for (int i = 0; i < 4; i++) {
            int gi = q0 + ty * 4 + i;
#pragma unroll
            for (int j = 0; j < 4; j++) {
                int gj = k0 + tx * 4 + j;
                float s_v = 50.0f * tanhf(sc[i][j] * scale * invcap);
                bool valid = (gj <= gi) && (gj > gi - WINDOW);
                sS[(ty * 4 + i) * 68 + tx * 4 + j] = valid ? s_v : NEG_INF_F;
            }
        }
        __syncthreads();

        // ---- phase 2: online softmax (4 threads per row, 16 cols each) ----
        float svals[16];
        float tmax = NEG_INF_F;
#pragma unroll
        for (int j = 0; j < 16; j++) {
            svals[j] = sS[myrow * 68 + dq * 16 + j];
            tmax = fmaxf(tmax, svals[j]);
        }
        tmax = fmaxf(tmax, __shfl_xor_sync(~0u, tmax, 1));
        tmax = fmaxf(tmax, __shfl_xor_sync(~0u, tmax, 2));
        float m_new = fmaxf(m_run, tmax);
        float corr = expf(m_run - m_new);  // 0 if m_run=-inf & m_new finite; 1 if both -inf
        float psum = 0.f;
#pragma unroll
        for (int j = 0; j < 16; j++) {
            // guard: masked entries must give exactly 0 even when m_new is still -1e30
            float p = (svals[j] > -1e29f) ? expf(svals[j] - m_new) : 0.f;
            sS[myrow * 68 + dq * 16 + j] = p;
            psum += p;
        }
        psum += __shfl_xor_sync(~0u, psum, 1);
        psum += __shfl_xor_sync(~0u, psum, 2);
        l_run = l_run * corr + psum;
        m_run = m_new;
        __syncwarp();  // p-values for my row were written by my own quad (same warp)

        // ---- phase 3: O += P @ V (thread owns row `myrow`, dims [dim0, dim0+32)) ----
#pragma unroll
        for (int i = 0; i < 32; i++) acc[i] *= corr;
        for (int t = 0; t < 64; t++) {
            float p = sS[myrow * 68 + t];
#pragma unroll
            for (int i = 0; i < 32; i += 4) {
                float4 vv = *(float4*)&sV[t * 128 + dim0 + i];
                acc[i] += p * vv.x;
                acc[i + 1] += p * vv.y;
                acc[i + 2] += p * vv.z;
                acc[i + 3] += p * vv.w;
            }
        }
    }

    const float invl = 1.f / l_run;
    size_t orow = ((size_t)b * SEQ + q0 + myrow) * (size_t)(HQ * HD) + (size_t)h * HD + dim0;
#pragma unroll
    for (int i = 0; i < 32; i += 4) {
        float4 v = make_float4(acc[i] * invl, acc[i + 1] * invl,
                               acc[i + 2] * invl, acc[i + 3] * invl);
        *(float4*)&O[orow + i] = v;
    }
}

// ---------------- launch ----------------
extern "C" void kernel_launch(void* const* d_in, const int* in_sizes, int n_in,
                              void* d_out, int out_size) {
    const float* x = (const float*)d_in[0];
    const float* gamma = (const float*)d_in[1];
    const float* Wq = (const float*)d_in[2];
    const float* Wk = (const float*)d_in[3];
    const float* Wv = (const float*)d_in[4];
    const float* Wo = (const float*)d_in[5];
    float* out = (float*)d_out;

    float *xn, *q, *k, *v, *attn, *cosT, *sinT;
    cudaGetSymbolAddress((void**)&xn, g_xn);
    cudaGetSymbolAddress((void**)&q, g_q);
    cudaGetSymbolAddress((void**)&k, g_k);
    cudaGetSymbolAddress((void**)&v, g_v);
    cudaGetSymbolAddress((void**)&attn, g_attn);
    cudaGetSymbolAddress((void**)&cosT, g_cos);
    cudaGetSymbolAddress((void**)&sinT, g_sin);

    cudaFuncSetAttribute(attn_kernel, cudaFuncAttributeMaxDynamicSharedMemorySize, ATT_SMEM);

    const int M = BATCH * SEQ;  // 4096

    // 1) RMSNorm
    rmsnorm_kernel<<<M, 256>>>(x, gamma, xn);

    // 2) RoPE tables
    rope_table_kernel<<<(SEQ * 64 + 255) / 256, 256>>>(cosT, sinT);

    // 3) QKV projections
    {
        dim3 gq(HQ * HD / BN, M / BM);
        gemm_kernel<<<gq, 256>>>(xn, Wq, nullptr, q, M, HQ * HD, HIDDEN);
        dim3 gk(HKV * HD / BN, M / BM);
        gemm_kernel<<<gk, 256>>>(xn, Wk, nullptr, k, M, HKV * HD, HIDDEN);
        gemm_kernel<<<gk, 256>>>(xn, Wv, nullptr, v, M, HKV * HD, HIDDEN);
    }

    // 4) RoPE apply (in place)
    {
        long tq = (long)M * HQ * 64;
        rope_apply_kernel<<<(int)((tq + 255) / 256), 256>>>(q, HQ, tq);
        long tk = (long)M * HKV * 64;
        rope_apply_kernel<<<(int)((tk + 255) / 256), 256>>>(k, HKV, tk);
    }

    // 5) attention
    {
        dim3 ga(SEQ / 64, HQ, BATCH);
        attn_kernel<<<ga, 256, ATT_SMEM>>>(q, k, v, attn);
    }

    // 6) output projection + residual
    {
        dim3 go(HIDDEN / BN, M / BM);
        gemm_kernel<<<go, 256>>>(attn, Wo, x, out, M, HIDDEN, HIDDEN);
    }
}

// round 4
// speedup vs baseline: 1.4906x; 1.4899x over previous
#include <cuda_runtime.h>
#include <cuda_bf16.h>
#include <math.h>
#include <stdint.h>

#define SEQ 2048
#define BATCH 2
#define HIDDEN 4096
#define HD 128
#define HQ 32
#define HKV 8
#define WINDOW 1024
#define NEG_INF_F (-1e30f)
#define MROWS (BATCH * SEQ) /* 4096 */
#define NQ (HQ * HD)        /* 4096 */
#define NKV (HKV * HD)      /* 1024 */

// ---------------- scratch (static device arrays; no allocations) ----------------
__device__ __nv_bfloat16 g_xn_h[(size_t)MROWS * HIDDEN];
__device__ __nv_bfloat16 g_xn_l[(size_t)MROWS * HIDDEN];
__device__ __nv_bfloat16 g_wqT_h[(size_t)NQ * HIDDEN];
__device__ __nv_bfloat16 g_wqT_l[(size_t)NQ * HIDDEN];
__device__ __nv_bfloat16 g_wkT_h[(size_t)NKV * HIDDEN];
__device__ __nv_bfloat16 g_wkT_l[(size_t)NKV * HIDDEN];
__device__ __nv_bfloat16 g_wvT_h[(size_t)NKV * HIDDEN];
__device__ __nv_bfloat16 g_wvT_l[(size_t)NKV * HIDDEN];
__device__ __nv_bfloat16 g_woT_h[(size_t)HIDDEN * NQ];
__device__ __nv_bfloat16 g_woT_l[(size_t)HIDDEN * NQ];
__device__ float g_q[(size_t)MROWS * NQ];
__device__ float g_k[(size_t)MROWS * NKV];
__device__ float g_v[(size_t)MROWS * NKV];
__device__ __nv_bfloat16 g_at_h[(size_t)MROWS * NQ];
__device__ __nv_bfloat16 g_at_l[(size_t)MROWS * NQ];
__device__ float g_cos[SEQ * 64];
__device__ float g_sin[SEQ * 64];

// ---------------- PTX helpers (baseline sm_80+ ISA only) ----------------
__device__ __forceinline__ uint32_t smem_u32(const void* p) {
    uint32_t a;
    asm("{ .reg .u64 t; cvta.to.shared.u64 t, %1; cvt.u32.u64 %0, t; }" : "=r"(a) : "l"(p));
    return a;
}
__device__ __forceinline__ void cp16(uint32_t s, const void* g) {
    asm volatile("cp.async.cg.shared.global [%0], [%1], 16;" :: "r"(s), "l"(g));
}
__device__ __forceinline__ void cp_commit() {
    asm volatile("cp.async.commit_group;" ::: "memory");
}
__device__ __forceinline__ void cp_wait0() {
    asm volatile("cp.async.wait_group 0;" ::: "memory");
}
__device__ __forceinline__ void cp_wait1() {
    asm volatile("cp.async.wait_group 1;" ::: "memory");
}
#define LDSM4(r0, r1, r2, r3, a) \
    asm volatile("ldmatrix.sync.aligned.m8n8.x4.shared.b16 {%0,%1,%2,%3}, [%4];" \
                 : "=r"(r0), "=r"(r1), "=r"(r2), "=r"(r3) : "r"(a))

__device__ __forceinline__ void mma16816(float* d, const uint32_t* a, uint32_t b0, uint32_t b1) {
    asm volatile(
        "mma.sync.aligned.m16n8k16.row.col.f32.bf16.bf16.f32 "
        "{%0,%1,%2,%3}, {%4,%5,%6,%7}, {%8,%9}, {%0,%1,%2,%3};"
        : "+f"(d[0]), "+f"(d[1]), "+f"(d[2]), "+f"(d[3])
        : "r"(a[0]), "r"(a[1]), "r"(a[2]), "r"(a[3]), "r"(b0), "r"(b1));
}

__device__ __forceinline__ void split2(float x, __nv_bfloat16& h, __nv_bfloat16& l) {
    h = __float2bfloat16_rn(x);
    l = __float2bfloat16_rn(x - __bfloat162float(h));
}

// ---------------- RMSNorm -> bf16 hi/lo split ----------------
__global__ __launch_bounds__(256) void rmsnorm_kernel(
    const float* __restrict__ x, const float* __restrict__ gamma,
    __nv_bfloat16* __restrict__ xh, __nv_bfloat16* __restrict__ xl) {
    const int row = blockIdx.x;
    const float4* xr = (const float4*)(x + (size_t)row * HIDDEN);
    const float4* g4 = (const float4*)gamma;

    float ss = 0.f;
    float4 v[4];
#pragma unroll
    for (int i = 0; i < 4; i++) {
        v[i] = xr[threadIdx.x + 256 * i];
        ss += v[i].x * v[i].x + v[i].y * v[i].y + v[i].z * v[i].z + v[i].w * v[i].w;
    }
#pragma unroll
    for (int o = 16; o > 0; o >>= 1) ss += __shfl_xor_sync(~0u, ss, o);
    __shared__ float sred[8];
    if ((threadIdx.x & 31) == 0) sred[threadIdx.x >> 5] = ss;
    __syncthreads();
    float tot = 0.f;
#pragma unroll
    for (int i = 0; i < 8; i++) tot += sred[i];

    const float inv = rsqrtf(tot / (float)HIDDEN + 1e-5f);
    size_t rb = (size_t)row * HIDDEN;
#pragma unroll
    for (int i = 0; i < 4; i++) {
        float4 g = g4[threadIdx.x + 256 * i];
        float o0 = v[i].x * inv * g.x, o1 = v[i].y * inv * g.y;
        float o2 = v[i].z * inv * g.z, o3 = v[i].w * inv * g.w;
        size_t e = rb + (size_t)(threadIdx.x + 256 * i) * 4;
        __nv_bfloat16 h0, l0, h1, l1, h2, l2, h3, l3;
        split2(o0, h0, l0); split2(o1, h1, l1); split2(o2, h2, l2); split2(o3, h3, l3);
        __nv_bfloat162 hh01; hh01.x = h0; hh01.y = h1;
        __nv_bfloat162 hh23; hh23.x = h2; hh23.y = h3;
        __nv_bfloat162 ll01; ll01.x = l0; ll01.y = l1;
        __nv_bfloat162 ll23; ll23.x = l2; ll23.y = l3;
        *(__nv_bfloat162*)(xh + e) = hh01;
        *(__nv_bfloat162*)(xh + e + 2) = hh23;
        *(__nv_bfloat162*)(xl + e) = ll01;
        *(__nv_bfloat162*)(xl + e + 2) = ll23;
    }
}

// ---------------- weight transpose + split: W[K,N] -> T[N,K] hi/lo ----------------
__global__ __launch_bounds__(256) void tsplit_kernel(
    const float* __restrict__ W, __nv_bfloat16* __restrict__ Th,
    __nv_bfloat16* __restrict__ Tl, int K, int N) {
    __shared__ __nv_bfloat16 sh[64][68];
    __shared__ __nv_bfloat16 sl[64][68];
    const int k0 = blockIdx.x * 64, n0 = blockIdx.y * 64;
    const int tid = threadIdx.x;

    for (int i = tid; i < 64 * 16; i += 256) {
        int r = i >> 4;
        int c4 = (i & 15) << 2;
        float4 w = *(const float4*)&W[(size_t)(k0 + r) * N + n0 + c4];
        split2(w.x, sh[c4 + 0][r], sl[c4 + 0][r]);
        split2(w.y, sh[c4 + 1][r], sl[c4 + 1][r]);
        split2(w.z, sh[c4 + 2][r], sl[c4 + 2][r]);
        split2(w.w, sh[c4 + 3][r], sl[c4 + 3][r]);
    }
    __syncthreads();
    for (int i = tid; i < 64 * 32; i += 256) {
        int n = i >> 5, kk2 = (i & 31) << 1;
        size_t off = (size_t)(n0 + n) * K + k0 + kk2;
        __nv_bfloat162 h; h.x = sh[n][kk2]; h.y = sh[n][kk2 + 1];
        __nv_bfloat162 l; l.x = sl[n][kk2]; l.y = sl[n][kk2 + 1];
        *(__nv_bfloat162*)(Th + off) = h;
        *(__nv_bfloat162*)(Tl + off) = l;
    }
}

// ---------------- mma.sync GEMM: C[M,N] = A[M,K] @ T[N,K]^T (+R), 3-term bf16 split ----------------
// Tile 128x128, BK=64 (128B SW128 rows), cp.async double buffer.
// Smem layout per buffer (64KB): Ah @0, Al @16K, Bh @32K, Bl @48K.
#define GEMM_SMEM (2 * 65536)

__device__ __forceinline__ void load_sub(uint32_t sdst, const __nv_bfloat16* src,
                                         int rbase, int K, int k0, int tid) {
#pragma unroll
    for (int p = 0; p < 4; p++) {
        int u = tid + (p << 8);
        int r = u >> 3, c16 = u & 7;
        const char* g = (const char*)(src + (size_t)(rbase + r) * K + k0) + (c16 << 4);
        cp16(sdst + r * 128 + ((c16 ^ (r & 7)) << 4), g);
    }
}

__global__ __launch_bounds__(256) void gemm_mma(
    const __nv_bfloat16* __restrict__ Ah, const __nv_bfloat16* __restrict__ Al,
    const __nv_bfloat16* __restrict__ Bh, const __nv_bfloat16* __restrict__ Bl,
    const float* __restrict__ R, float* __restrict__ C, int M, int N, int K) {
    extern __shared__ char smraw[];
    const uint32_t sbase = smem_u32(smraw);
    const int tid = threadIdx.x;
    const int lane = tid & 31, wid = tid >> 5;
    const int row0 = blockIdx.y * 128, col0 = blockIdx.x * 128;
    const int wm = (wid & 1) * 64, wn = (wid >> 1) * 32;

    float acc[4][4][4];
#pragma unroll
    for (int i = 0; i < 4; i++)
#pragma unroll
        for (int j = 0; j < 4; j++)
#pragma unroll
            for (int r = 0; r < 4; r++) acc[i][j][r] = 0.f;

    const int NC = K >> 6;

    // prologue: load chunk 0 into buffer 0
    load_sub(sbase,         Ah, row0, K, 0, tid);
    load_sub(sbase + 16384, Al, row0, K, 0, tid);
    load_sub(sbase + 32768, Bh, col0, K, 0, tid);
    load_sub(sbase + 49152, Bl, col0, K, 0, tid);
    cp_commit();

    // precomputed ldmatrix lane geometry
    const int a_r = lane & 15;            // row within 16-row atom group
    const int a_ch = lane >> 4;           // k-half (0/1)
    const int b_n = ((lane >> 4) << 3) + (lane & 7);  // n offset within 16
    const int b_kh = (lane >> 3) & 1;     // k-half

    for (int c = 0; c < NC; c++) {
        const int buf = c & 1;
        if (c + 1 < NC) {
            const uint32_t nb = sbase + (buf ^ 1) * 65536;
            const int k0 = (c + 1) << 6;
            load_sub(nb,         Ah, row0, K, k0, tid);
            load_sub(nb + 16384, Al, row0, K, k0, tid);
            load_sub(nb + 32768, Bh, col0, K, k0, tid);
            load_sub(nb + 49152, Bl, col0, K, k0, tid);
            cp_commit();
            cp_wait1();
        } else {
            cp_wait0();
        }
        __syncthreads();

        const uint32_t sb = sbase + buf * 65536;
#pragma unroll
        for (int ks = 0; ks < 4; ks++) {
            uint32_t aH[4][4], aL[4][4], bH[2][4], bL[2][4];
#pragma unroll
            for (int i = 0; i < 4; i++) {
                int r = wm + i * 16 + a_r;
                uint32_t cl = (uint32_t)((ks * 2 + a_ch) ^ (r & 7)) << 4;
                uint32_t ad = sb + r * 128 + cl;
                LDSM4(aH[i][0], aH[i][1], aH[i][2], aH[i][3], ad);
                LDSM4(aL[i][0], aL[i][1], aL[i][2], aL[i][3], ad + 16384);
            }
#pragma unroll
            for (int j = 0; j < 2; j++) {
                int r = wn + j * 16 + b_n;
                uint32_t cl = (uint32_t)((ks * 2 + b_kh) ^ (r & 7)) << 4;
                uint32_t bd = sb + 32768 + r * 128 + cl;
                LDSM4(bH[j][0], bH[j][1], bH[j][2], bH[j][3], bd);
                LDSM4(bL[j][0], bL[j][1], bL[j][2], bL[j][3], bd + 16384);
            }
#pragma unroll
            for (int i = 0; i < 4; i++) {
#pragma unroll
                for (int jn = 0; jn < 4; jn++) {
                    uint32_t h0 = bH[jn >> 1][(jn & 1) * 2], h1 = bH[jn >> 1][(jn & 1) * 2 + 1];
                    uint32_t l0 = bL[jn >> 1][(jn & 1) * 2], l1 = bL[jn >> 1][(jn & 1) * 2 + 1];
                    mma16816(acc[i][jn], aH[i], h0, h1);
                    mma16816(acc[i][jn], aH[i], l0, l1);
                    mma16816(acc[i][jn], aL[i], h0, h1);
                }
            }
        }
        __syncthreads();
    }

    // epilogue
    const int mrow = lane >> 2, ncol = (lane & 3) * 2;
#pragma unroll
    for (int i = 0; i < 4; i++) {
        int gr = row0 + wm + i * 16 + mrow;
#pragma unroll
        for (int jn = 0; jn < 4; jn++) {
            int gc = col0 + wn + jn * 8 + ncol;
            float2 v0 = make_float2(acc[i][jn][0], acc[i][jn][1]);
            float2 v1 = make_float2(acc[i][jn][2], acc[i][jn][3]);
            if (R) {
                float2 r0 = *(const float2*)&R[(size_t)gr * N + gc];
                float2 r1 = *(const float2*)&R[(size_t)(gr + 8) * N + gc];
                v0.x += r0.x; v0.y += r0.y;
                v1.x += r1.x; v1.y += r1.y;
            }
            *(float2*)&C[(size_t)gr * N + gc] = v0;
            *(float2*)&C[(size_t)(gr + 8) * N + gc] = v1;
        }
    }
}

// ---------------- RoPE tables ----------------
__global__ void rope_table_kernel(float* __restrict__ cosT, float* __restrict__ sinT) {
    int idx = blockIdx.x * blockDim.x + threadIdx.x;
    if (idx >= SEQ * 64) return;
    int s = idx >> 6, i = idx & 63;
    double ang = (double)s * pow(10000.0, -(double)i / 64.0);
    double sn, cs;
    sincos(ang, &sn, &cs);
    cosT[idx] = (float)cs;
    sinT[idx] = (float)sn;
}

// ---------------- RoPE apply (in place, fp32) ----------------
__global__ __launch_bounds__(256) void rope_apply_kernel(
    float* __restrict__ t, int nheads, long total) {
    long idx = (long)blockIdx.x * blockDim.x + threadIdx.x;
    if (idx >= total) return;
    int i = (int)(idx & 63);
    long vi = idx >> 6;
    int s = (int)((vi / nheads) % SEQ);
    float c = g_cos[s * 64 + i];
    float sn = g_sin[s * 64 + i];
    float* p = t + vi * HD;
    float a = p[i], b = p[i + 64];
    p[i] = a * c - b * sn;
    p[i + 64] = b * c + a * sn;
}

// ---------------- flash attention (windowed causal + tanh cap), bf16-split output ----------------
#define ATT_SMEM ((64 * 128 + 64 * 132 + 64 * 128 + 64 * 68) * 4)
__global__ __launch_bounds__(256) void attn_kernel(
    const float* __restrict__ Q, const float* __restrict__ K,
    const float* __restrict__ V, __nv_bfloat16* __restrict__ Oh,
    __nv_bfloat16* __restrict__ Ol) {
    extern __shared__ float sm[];
    float* sQ = sm;
    float* sK = sQ + 64 * 128;
    float* sV = sK + 64 * 132;
    float* sS = sV + 64 * 128;

    const int qt = blockIdx.x, h = blockIdx.y, b = blockIdx.z;
    const int g = h >> 2;
    const int q0 = qt * 64;
    const int tid = threadIdx.x;
    const int tx = tid & 15, ty = tid >> 4;
    const int myrow = tid >> 2, dq = tid & 3;
    const int dim0 = dq * 32;

    for (int i = tid; i < 64 * 32; i += 256) {
        int r = i >> 5, c = (i & 31) << 2;
        *(float4*)&sQ[r * 128 + c] =
            *(const float4*)&Q[(((size_t)b * SEQ + q0 + r) * HQ + h) * HD + c];
    }

    float acc[32];
#pragma unroll
    for (int i = 0; i < 32; i++) acc[i] = 0.f;
    float m_run = NEG_INF_F, l_run = 0.f;

    const int kt_lo = max(0, q0 - WINDOW + 1) >> 6;
    const float zs = 0.08838834764831845f / 50.0f;  // scale / CAP

    for (int kt = kt_lo; kt <= qt; kt++) {
        const int k0 = kt * 64;
        __syncthreads();
        for (int i = tid; i < 64 * 32; i += 256) {
            int r = i >> 5, c = (i & 31) << 2;
            size_t base = (((size_t)b * SEQ + k0 + r) * HKV + g) * HD + c;
            *(float4*)&sK[r * 132 + c] = *(const float4*)&K[base];
            *(float4*)&sV[r * 128 + c] = *(const float4*)&V[base];
        }
        __syncthreads();

        float sc[4][4];
#pragma unroll
        for (int i = 0; i < 4; i++)
#pragma unroll
            for (int j = 0; j < 4; j++) sc[i][j] = 0.f;

#pragma unroll 4
        for (int d4 = 0; d4 < 32; d4++) {
            float4 qv[4], kv[4];
#pragma unroll
            for (int i = 0; i < 4; i++) qv[i] = *(float4*)&sQ[(ty * 4 + i) * 128 + d4 * 4];
#pragma unroll
            for (int j = 0; j < 4; j++) kv[j] = *(float4*)&sK[(tx * 4 + j) * 132 + d4 * 4];
#pragma unroll
            for (int i = 0; i < 4; i++)
#pragma unroll
                for (int j = 0; j < 4; j++)
                    sc[i][j] += qv[i].x * kv[j].x + qv[i].y * kv[j].y +
                                qv[i].z * kv[j].z + qv[i].w * kv[j].w;
        }

#pragma unroll
        for (int i = 0; i < 4; i++) {
            int gi = q0 + ty * 4 + i;
#pragma unroll
            for (int j = 0; j < 4; j++) {
                int gj = k0 + tx * 4 + j;
                float t = __expf(2.0f * sc[i][j] * zs);
                float s_v = 50.0f * (1.0f - 2.0f / (t + 1.0f));
                bool valid = (gj <= gi) && (gj > gi - WINDOW);
                sS[(ty * 4 + i) * 68 + tx * 4 + j] = valid ? s_v : NEG_INF_F;
            }
        }
        __syncthreads();

        float svals[16];
        float tmax = NEG_INF_F;
#pragma unroll
        for (int j = 0; j < 16; j++) {
            svals[j] = sS[myrow * 68 + dq * 16 + j];
            tmax = fmaxf(tmax, svals[j]);
        }
        tmax = fmaxf(tmax, __shfl_xor_sync(~0u, tmax, 1));
        tmax = fmaxf(tmax, __shfl_xor_sync(~0u, tmax, 2));
        float m_new = fmaxf(m_run, tmax);
        float corr = __expf(m_run - m_new);
        float psum = 0.f;
#pragma unroll
        for (int j = 0; j < 16; j++) {
            float p = (svals[j] > -1e29f) ? __expf(svals[j] - m_new) : 0.f;
            sS[myrow * 68 + dq * 16 + j] = p;
            psum += p;
        }
        psum += __shfl_xor_sync(~0u, psum, 1);
        psum += __shfl_xor_sync(~0u, psum, 2);
        l_run = l_run * corr + psum;
        m_run = m_new;
        __syncwarp();

#pragma unroll
        for (int i = 0; i < 32; i++) acc[i] *= corr;
        for (int t = 0; t < 64; t++) {
            float p = sS[myrow * 68 + t];
#pragma unroll
            for (int i = 0; i < 32; i += 4) {
                float4 vv = *(float4*)&sV[t * 128 + dim0 + i];
                acc[i] += p * vv.x;
                acc[i + 1] += p * vv.y;
                acc[i + 2] += p * vv.z;
                acc[i + 3] += p * vv.w;
            }
        }
    }

    const float invl = 1.f / l_run;
    size_t orow = ((size_t)b * SEQ + q0 + myrow) * (size_t)NQ + (size_t)h * HD + dim0;
#pragma unroll
    for (int i = 0; i < 32; i += 2) {
        float a0 = acc[i] * invl, a1 = acc[i + 1] * invl;
        __nv_bfloat16 h0, l0, h1, l1;
        split2(a0, h0, l0);
        split2(a1, h1, l1);
        __nv_bfloat162 hh; hh.x = h0; hh.y = h1;
        __nv_bfloat162 ll; ll.x = l0; ll.y = l1;
        *(__nv_bfloat162*)(Oh + orow + i) = hh;
        *(__nv_bfloat162*)(Ol + orow + i) = ll;
    }
}

// ---------------- launch ----------------
extern "C" void kernel_launch(void* const* d_in, const int* in_sizes, int n_in,
                              void* d_out, int out_size) {
    const float* x = (const float*)d_in[0];
    const float* gamma = (const float*)d_in[1];
    const float* Wq = (const float*)d_in[2];
    const float* Wk = (const float*)d_in[3];
    const float* Wv = (const float*)d_in[4];
    const float* Wo = (const float*)d_in[5];
    float* out = (float*)d_out;

    __nv_bfloat16 *xnh, *xnl, *wqh, *wql, *wkh, *wkl, *wvh, *wvl, *woh, *wol, *ath, *atl;
    float *q, *k, *v, *cosT, *sinT;
    cudaGetSymbolAddress((void**)&xnh, g_xn_h);
    cudaGetSymbolAddress((void**)&xnl, g_xn_l);
    cudaGetSymbolAddress((void**)&wqh, g_wqT_h);
    cudaGetSymbolAddress((void**)&wql, g_wqT_l);
    cudaGetSymbolAddress((void**)&wkh, g_wkT_h);
    cudaGetSymbolAddress((void**)&wkl, g_wkT_l);
    cudaGetSymbolAddress((void**)&wvh, g_wvT_h);
    cudaGetSymbolAddress((void**)&wvl, g_wvT_l);
    cudaGetSymbolAddress((void**)&woh, g_woT_h);
    cudaGetSymbolAddress((void**)&wol, g_woT_l);
    cudaGetSymbolAddress((void**)&ath, g_at_h);
    cudaGetSymbolAddress((void**)&atl, g_at_l);
    cudaGetSymbolAddress((void**)&q, g_q);
    cudaGetSymbolAddress((void**)&k, g_k);
    cudaGetSymbolAddress((void**)&v, g_v);
    cudaGetSymbolAddress((void**)&cosT, g_cos);
    cudaGetSymbolAddress((void**)&sinT, g_sin);

    cudaFuncSetAttribute(attn_kernel, cudaFuncAttributeMaxDynamicSharedMemorySize, ATT_SMEM);
    cudaFuncSetAttribute(gemm_mma, cudaFuncAttributeMaxDynamicSharedMemorySize, GEMM_SMEM);

    // 1) RMSNorm -> split
    rmsnorm_kernel<<<MROWS, 256>>>(x, gamma, xnh, xnl);

    // 2) RoPE tables
    rope_table_kernel<<<(SEQ * 64 + 255) / 256, 256>>>(cosT, sinT);

    // 3) weight transpose + split
    {
        dim3 gq(HIDDEN / 64, NQ / 64);
        tsplit_kernel<<<gq, 256>>>(Wq, wqh, wql, HIDDEN, NQ);
        dim3 gk(HIDDEN / 64, NKV / 64);
        tsplit_kernel<<<gk, 256>>>(Wk, wkh, wkl, HIDDEN, NKV);
        tsplit_kernel<<<gk, 256>>>(Wv, wvh, wvl, HIDDEN, NKV);
        dim3 go(NQ / 64, HIDDEN / 64);
        tsplit_kernel<<<go, 256>>>(Wo, woh, wol, NQ, HIDDEN);
    }

    // 4) QKV projections (tensor cores via mma.sync)
    {
        dim3 gq(NQ / 128, MROWS / 128);
        gemm_mma<<<gq, 256, GEMM_SMEM>>>(xnh, xnl, wqh, wql, (const float*)0, q, MROWS, NQ, HIDDEN);
        dim3 gk(NKV / 128, MROWS / 128);
        gemm_mma<<<gk, 256, GEMM_SMEM>>>(xnh, xnl, wkh, wkl, (const float*)0, k, MROWS, NKV, HIDDEN);
        gemm_mma<<<gk, 256, GEMM_SMEM>>>(xnh, xnl, wvh, wvl, (const float*)0, v, MROWS, NKV, HIDDEN);
    }

    // 5) RoPE apply
    {
        long tq = (long)MROWS * HQ * 64;
        rope_apply_kernel<<<(int)((tq + 255) / 256), 256>>>(q, HQ, tq);
        long tk = (long)MROWS * HKV * 64;
        rope_apply_kernel<<<(int)((tk + 255) / 256), 256>>>(k, HKV, tk);
    }

    // 6) attention -> split output
    {
        dim3 ga(SEQ / 64, HQ, BATCH);
        attn_kernel<<<ga, 256, ATT_SMEM>>>(q, k, v, ath, atl);
    }

    // 7) output projection + residual (tensor cores via mma.sync)
    {
        dim3 go(HIDDEN / 128, MROWS / 128);
        gemm_mma<<<go, 256, GEMM_SMEM>>>(ath, atl, woh, wol, x, out, MROWS, HIDDEN, NQ);
    }
}

// round 5
// speedup vs baseline: 5.1806x; 3.4756x over previous
#include <cuda_runtime.h>
#include <cuda_bf16.h>
#include <math.h>
#include <stdint.h>

#define SEQ 2048
#define BATCH 2
#define HIDDEN 4096
#define HD 128
#define HQ 32
#define HKV 8
#define WINDOW 1024
#define NEG_INF_F (-1e30f)
#define MROWS (BATCH * SEQ) /* 4096 */
#define NQ (HQ * HD)        /* 4096 */
#define NKV (HKV * HD)      /* 1024 */

// ---------------- scratch (static device arrays; no allocations) ----------------
__device__ __nv_bfloat16 g_xn_h[(size_t)MROWS * HIDDEN];
__device__ __nv_bfloat16 g_xn_l[(size_t)MROWS * HIDDEN];
__device__ __nv_bfloat16 g_wqT_h[(size_t)NQ * HIDDEN];
__device__ __nv_bfloat16 g_wqT_l[(size_t)NQ * HIDDEN];
__device__ __nv_bfloat16 g_wkT_h[(size_t)NKV * HIDDEN];
__device__ __nv_bfloat16 g_wkT_l[(size_t)NKV * HIDDEN];
__device__ __nv_bfloat16 g_wvT_h[(size_t)NKV * HIDDEN];
__device__ __nv_bfloat16 g_wvT_l[(size_t)NKV * HIDDEN];
__device__ __nv_bfloat16 g_woT_h[(size_t)HIDDEN * NQ];
__device__ __nv_bfloat16 g_woT_l[(size_t)HIDDEN * NQ];
__device__ float g_q[(size_t)MROWS * NQ];
__device__ float g_k[(size_t)MROWS * NKV];
__device__ float g_v[(size_t)MROWS * NKV];
// head-major bf16 splits for attention
__device__ __nv_bfloat16 g_qh[(size_t)BATCH * HQ * SEQ * HD];
__device__ __nv_bfloat16 g_ql[(size_t)BATCH * HQ * SEQ * HD];
__device__ __nv_bfloat16 g_kh[(size_t)BATCH * HKV * SEQ * HD];
__device__ __nv_bfloat16 g_kl[(size_t)BATCH * HKV * SEQ * HD];
__device__ __nv_bfloat16 g_vh[(size_t)BATCH * HKV * SEQ * HD];
__device__ __nv_bfloat16 g_vl[(size_t)BATCH * HKV * SEQ * HD];
__device__ __nv_bfloat16 g_at_h[(size_t)MROWS * NQ];
__device__ __nv_bfloat16 g_at_l[(size_t)MROWS * NQ];
__device__ float g_cos[SEQ * 64];
__device__ float g_sin[SEQ * 64];

// ---------------- PTX helpers (baseline sm_80+ ISA only) ----------------
__device__ __forceinline__ uint32_t smem_u32(const void* p) {
    uint32_t a;
    asm("{ .reg .u64 t; cvta.to.shared.u64 t, %1; cvt.u32.u64 %0, t; }" : "=r"(a) : "l"(p));
    return a;
}
__device__ __forceinline__ void cp16(uint32_t s, const void* g) {
    asm volatile("cp.async.cg.shared.global [%0], [%1], 16;" :: "r"(s), "l"(g));
}
__device__ __forceinline__ void cp_commit() {
    asm volatile("cp.async.commit_group;" ::: "memory");
}
__device__ __forceinline__ void cp_wait0() {
    asm volatile("cp.async.wait_group 0;" ::: "memory");
}
__device__ __forceinline__ void cp_wait1() {
    asm volatile("cp.async.wait_group 1;" ::: "memory");
}
#define LDSM4(r0, r1, r2, r3, a) \
    asm volatile("ldmatrix.sync.aligned.m8n8.x4.shared.b16 {%0,%1,%2,%3}, [%4];" \
                 : "=r"(r0), "=r"(r1), "=r"(r2), "=r"(r3) : "r"(a))
#define LDSM4T(r0, r1, r2, r3, a) \
    asm volatile("ldmatrix.sync.aligned.m8n8.x4.trans.shared.b16 {%0,%1,%2,%3}, [%4];" \
                 : "=r"(r0), "=r"(r1), "=r"(r2), "=r"(r3) : "r"(a))

__device__ __forceinline__ void mma16816(float* d, const uint32_t* a, uint32_t b0, uint32_t b1) {
    asm volatile(
        "mma.sync.aligned.m16n8k16.row.col.f32.bf16.bf16.f32 "
        "{%0,%1,%2,%3}, {%4,%5,%6,%7}, {%8,%9}, {%0,%1,%2,%3};"
        : "+f"(d[0]), "+f"(d[1]), "+f"(d[2]), "+f"(d[3])
        : "r"(a[0]), "r"(a[1]), "r"(a[2]), "r"(a[3]), "r"(b0), "r"(b1));
}

__device__ __forceinline__ void split2(float x, __nv_bfloat16& h, __nv_bfloat16& l) {
    h = __float2bfloat16_rn(x);
    l = __float2bfloat16_rn(x - __bfloat162float(h));
}
__device__ __forceinline__ uint32_t packh2(float a, float b) {
    __nv_bfloat162 t;
    t.x = __float2bfloat16_rn(a);
    t.y = __float2bfloat16_rn(b);
    return *(uint32_t*)&t;
}

// ---------------- RMSNorm -> bf16 hi/lo split ----------------
__global__ __launch_bounds__(256) void rmsnorm_kernel(
    const float* __restrict__ x, const float* __restrict__ gamma,
    __nv_bfloat16* __restrict__ xh, __nv_bfloat16* __restrict__ xl) {
    const int row = blockIdx.x;
    const float4* xr = (const float4*)(x + (size_t)row * HIDDEN);
    const float4* g4 = (const float4*)gamma;

    float ss = 0.f;
    float4 v[4];
#pragma unroll
    for (int i = 0; i < 4; i++) {
        v[i] = xr[threadIdx.x + 256 * i];
        ss += v[i].x * v[i].x + v[i].y * v[i].y + v[i].z * v[i].z + v[i].w * v[i].w;
    }
#pragma unroll
    for (int o = 16; o > 0; o >>= 1) ss += __shfl_xor_sync(~0u, ss, o);
    __shared__ float sred[8];
    if ((threadIdx.x & 31) == 0) sred[threadIdx.x >> 5] = ss;
    __syncthreads();
    float tot = 0.f;
#pragma unroll
    for (int i = 0; i < 8; i++) tot += sred[i];

    const float inv = rsqrtf(tot / (float)HIDDEN + 1e-5f);
    size_t rb = (size_t)row * HIDDEN;
#pragma unroll
    for (int i = 0; i < 4; i++) {
        float4 g = g4[threadIdx.x + 256 * i];
        float o0 = v[i].x * inv * g.x, o1 = v[i].y * inv * g.y;
        float o2 = v[i].z * inv * g.z, o3 = v[i].w * inv * g.w;
        size_t e = rb + (size_t)(threadIdx.x + 256 * i) * 4;
        __nv_bfloat16 h0, l0, h1, l1, h2, l2, h3, l3;
        split2(o0, h0, l0); split2(o1, h1, l1); split2(o2, h2, l2); split2(o3, h3, l3);
        __nv_bfloat162 hh01; hh01.x = h0; hh01.y = h1;
        __nv_bfloat162 hh23; hh23.x = h2; hh23.y = h3;
        __nv_bfloat162 ll01; ll01.x = l0; ll01.y = l1;
        __nv_bfloat162 ll23; ll23.x = l2; ll23.y = l3;
        *(__nv_bfloat162*)(xh + e) = hh01;
        *(__nv_bfloat162*)(xh + e + 2) = hh23;
        *(__nv_bfloat162*)(xl + e) = ll01;
        *(__nv_bfloat162*)(xl + e + 2) = ll23;
    }
}

// ---------------- weight transpose + split: W[K,N] -> T[N,K] hi/lo ----------------
__global__ __launch_bounds__(256) void tsplit_kernel(
    const float* __restrict__ W, __nv_bfloat16* __restrict__ Th,
    __nv_bfloat16* __restrict__ Tl, int K, int N) {
    __shared__ __nv_bfloat16 sh[64][68];
    __shared__ __nv_bfloat16 sl[64][68];
    const int k0 = blockIdx.x * 64, n0 = blockIdx.y * 64;
    const int tid = threadIdx.x;

    for (int i = tid; i < 64 * 16; i += 256) {
        int r = i >> 4;
        int c4 = (i & 15) << 2;
        float4 w = *(const float4*)&W[(size_t)(k0 + r) * N + n0 + c4];
        split2(w.x, sh[c4 + 0][r], sl[c4 + 0][r]);
        split2(w.y, sh[c4 + 1][r], sl[c4 + 1][r]);
        split2(w.z, sh[c4 + 2][r], sl[c4 + 2][r]);
        split2(w.w, sh[c4 + 3][r], sl[c4 + 3][r]);
    }
    __syncthreads();
    for (int i = tid; i < 64 * 32; i += 256) {
        int n = i >> 5, kk2 = (i & 31) << 1;
        size_t off = (size_t)(n0 + n) * K + k0 + kk2;
        __nv_bfloat162 h; h.x = sh[n][kk2]; h.y = sh[n][kk2 + 1];
        __nv_bfloat162 l; l.x = sl[n][kk2]; l.y = sl[n][kk2 + 1];
        *(__nv_bfloat162*)(Th + off) = h;
        *(__nv_bfloat162*)(Tl + off) = l;
    }
}

// ---------------- mma.sync GEMM (unchanged from R4) ----------------
#define GEMM_SMEM (2 * 65536)

__device__ __forceinline__ void load_sub(uint32_t sdst, const __nv_bfloat16* src,
                                         int rbase, int K, int k0, int tid) {
#pragma unroll
    for (int p = 0; p < 4; p++) {
        int u = tid + (p << 8);
        int r = u >> 3, c16 = u & 7;
        const char* g = (const char*)(src + (size_t)(rbase + r) * K + k0) + (c16 << 4);
        cp16(sdst + r * 128 + ((c16 ^ (r & 7)) << 4), g);
    }
}

__global__ __launch_bounds__(256) void gemm_mma(
    const __nv_bfloat16* __restrict__ Ah, const __nv_bfloat16* __restrict__ Al,
    const __nv_bfloat16* __restrict__ Bh, const __nv_bfloat16* __restrict__ Bl,
    const float* __restrict__ R, float* __restrict__ C, int M, int N, int K) {
    extern __shared__ char smraw[];
    const uint32_t sbase = smem_u32(smraw);
    const int tid = threadIdx.x;
    const int lane = tid & 31, wid = tid >> 5;
    const int row0 = blockIdx.y * 128, col0 = blockIdx.x * 128;
    const int wm = (wid & 1) * 64, wn = (wid >> 1) * 32;

    float acc[4][4][4];
#pragma unroll
    for (int i = 0; i < 4; i++)
#pragma unroll
        for (int j = 0; j < 4; j++)
#pragma unroll
            for (int r = 0; r < 4; r++) acc[i][j][r] = 0.f;

    const int NC = K >> 6;

    load_sub(sbase,         Ah, row0, K, 0, tid);
    load_sub(sbase + 16384, Al, row0, K, 0, tid);
    load_sub(sbase + 32768, Bh, col0, K, 0, tid);
    load_sub(sbase + 49152, Bl, col0, K, 0, tid);
    cp_commit();

    const int a_r = lane & 15;
    const int a_ch = lane >> 4;
    const int b_n = ((lane >> 4) << 3) + (lane & 7);
    const int b_kh = (lane >> 3) & 1;

    for (int c = 0; c < NC; c++) {
        const int buf = c & 1;
        if (c + 1 < NC) {
            const uint32_t nb = sbase + (buf ^ 1) * 65536;
            const int k0 = (c + 1) << 6;
            load_sub(nb,         Ah, row0, K, k0, tid);
            load_sub(nb + 16384, Al, row0, K, k0, tid);
            load_sub(nb + 32768, Bh, col0, K, k0, tid);
            load_sub(nb + 49152, Bl, col0, K, k0, tid);
            cp_commit();
            cp_wait1();
        } else {
            cp_wait0();
        }
        __syncthreads();

        const uint32_t sb = sbase + buf * 65536;
#pragma unroll
        for (int ks = 0; ks < 4; ks++) {
            uint32_t aH[4][4], aL[4][4], bH[2][4], bL[2][4];
#pragma unroll
            for (int i = 0; i < 4; i++) {
                int r = wm + i * 16 + a_r;
                uint32_t cl = (uint32_t)((ks * 2 + a_ch) ^ (r & 7)) << 4;
                uint32_t ad = sb + r * 128 + cl;
                LDSM4(aH[i][0], aH[i][1], aH[i][2], aH[i][3], ad);
                LDSM4(aL[i][0], aL[i][1], aL[i][2], aL[i][3], ad + 16384);
            }
#pragma unroll
            for (int j = 0; j < 2; j++) {
                int r = wn + j * 16 + b_n;
                uint32_t cl = (uint32_t)((ks * 2 + b_kh) ^ (r & 7)) << 4;
                uint32_t bd = sb + 32768 + r * 128 + cl;
                LDSM4(bH[j][0], bH[j][1], bH[j][2], bH[j][3], bd);
                LDSM4(bL[j][0], bL[j][1], bL[j][2], bL[j][3], bd + 16384);
            }
#pragma unroll
            for (int i = 0; i < 4; i++) {
#pragma unroll
                for (int jn = 0; jn < 4; jn++) {
                    uint32_t h0 = bH[jn >> 1][(jn & 1) * 2], h1 = bH[jn >> 1][(jn & 1) * 2 + 1];
                    uint32_t l0 = bL[jn >> 1][(jn & 1) * 2], l1 = bL[jn >> 1][(jn & 1) * 2 + 1];
                    mma16816(acc[i][jn], aH[i], h0, h1);
                    mma16816(acc[i][jn], aH[i], l0, l1);
                    mma16816(acc[i][jn], aL[i], h0, h1);
                }
            }
        }
        __syncthreads();
    }

    const int mrow = lane >> 2, ncol = (lane & 3) * 2;
#pragma unroll
    for (int i = 0; i < 4; i++) {
        int gr = row0 + wm + i * 16 + mrow;
#pragma unroll
        for (int jn = 0; jn < 4; jn++) {
            int gc = col0 + wn + jn * 8 + ncol;
            float2 v0 = make_float2(acc[i][jn][0], acc[i][jn][1]);
            float2 v1 = make_float2(acc[i][jn][2], acc[i][jn][3]);
            if (R) {
                float2 r0 = *(const float2*)&R[(size_t)gr * N + gc];
                float2 r1 = *(const float2*)&R[(size_t)(gr + 8) * N + gc];
                v0.x += r0.x; v0.y += r0.y;
                v1.x += r1.x; v1.y += r1.y;
            }
            *(float2*)&C[(size_t)gr * N + gc] = v0;
            *(float2*)&C[(size_t)(gr + 8) * N + gc] = v1;
        }
    }
}

// ---------------- RoPE tables ----------------
__global__ void rope_table_kernel(float* __restrict__ cosT, float* __restrict__ sinT) {
    int idx = blockIdx.x * blockDim.x + threadIdx.x;
    if (idx >= SEQ * 64) return;
    int s = idx >> 6, i = idx & 63;
    double ang = (double)s * pow(10000.0, -(double)i / 64.0);
    double sn, cs;
    sincos(ang, &sn, &cs);
    cosT[idx] = (float)cs;
    sinT[idx] = (float)sn;
}

// ---------------- RoPE + transpose to head-major + bf16 split ----------------
__global__ __launch_bounds__(256) void rope_split_kernel(
    const float* __restrict__ src, __nv_bfloat16* __restrict__ dh,
    __nv_bfloat16* __restrict__ dl, int nheads, long total) {
    long idx = (long)blockIdx.x * blockDim.x + threadIdx.x;
    if (idx >= total) return;
    int i = (int)(idx & 63);
    long t = idx >> 6;
    int s = (int)(t & (SEQ - 1));
    t >>= 11;
    int h = (int)(t % nheads);
    int b = (int)(t / nheads);
    const float* sp = src + ((size_t)b * SEQ + s) * (size_t)(nheads * HD) + (size_t)h * HD;
    float a = sp[i], bb = sp[i + 64];
    float c = g_cos[s * 64 + i], sn = g_sin[s * 64 + i];
    float o1 = a * c - bb * sn;
    float o2 = bb * c + a * sn;
    size_t d = (((size_t)b * nheads + h) * SEQ + s) * HD;
    __nv_bfloat16 h1, l1, h2, l2;
    split2(o1, h1, l1); split2(o2, h2, l2);
    dh[d + i] = h1; dl[d + i] = l1;
    dh[d + i + 64] = h2; dl[d + i + 64] = l2;
}

// ---------------- V transpose to head-major + bf16 split (no rope) ----------------
__global__ __launch_bounds__(256) void vsplit_kernel(
    const float* __restrict__ src, __nv_bfloat16* __restrict__ dh,
    __nv_bfloat16* __restrict__ dl, long total) {
    long idx = (long)blockIdx.x * blockDim.x + threadIdx.x;
    if (idx >= total) return;
    int i = (int)(idx & 127);
    long t = idx >> 7;
    int s = (int)(t & (SEQ - 1));
    t >>= 11;
    int h = (int)(t % HKV);
    int b = (int)(t / HKV);
    float v = src[((size_t)b * SEQ + s) * NKV + (size_t)h * HD + i];
    size_t d = (((size_t)b * HKV + h) * SEQ + s) * HD + i;
    __nv_bfloat16 hh, ll;
    split2(v, hh, ll);
    dh[d] = hh;
    dl[d] = ll;
}

// ---------------- attention via mma.sync ----------------
// grid (SEQ/128, HQ, B), 256 threads (8 warps x 16 q-rows).
// smem: Qh 32K | Ql 32K | 2x{Kh 16K|Kl 16K|Vh 16K|Vl 16K} = 192KB
#define AT_SMEM (196608)

__global__ __launch_bounds__(256) void attn_mma(
    const __nv_bfloat16* __restrict__ Qh, const __nv_bfloat16* __restrict__ Ql,
    const __nv_bfloat16* __restrict__ Kh, const __nv_bfloat16* __restrict__ Kl,
    const __nv_bfloat16* __restrict__ Vh, const __nv_bfloat16* __restrict__ Vl,
    __nv_bfloat16* __restrict__ Oh, __nv_bfloat16* __restrict__ Ol) {
    extern __shared__ char smraw[];
    const uint32_t S0 = smem_u32(smraw);
    const int tid = threadIdx.x;
    const int lane = tid & 31, wid = tid >> 5;
    const int qt = blockIdx.x, h = blockIdx.y, b = blockIdx.z;
    const int g = h >> 2;
    const int q0 = qt * 128;
    const int m0 = wid * 16;

    // ---- load Q (hi+lo) into swizzled smem ----
    {
        const char* qb_h = (const char*)(Qh + (((size_t)b * HQ + h) * SEQ + q0) * HD);
        const char* qb_l = (const char*)(Ql + (((size_t)b * HQ + h) * SEQ + q0) * HD);
#pragma unroll
        for (int p = 0; p < 8; p++) {
            int u = tid + (p << 8);
            int r = u >> 4, c = u & 15;
            uint32_t off = r * 256 + (uint32_t)((c ^ (r & 7)) << 4);
            cp16(S0 + off, qb_h + r * 256 + c * 16);
            cp16(S0 + 32768 + off, qb_l + r * 256 + c * 16);
        }
    }

    const size_t kvhead = ((size_t)b * HKV + g) * SEQ;
    const int kt_lo = max(0, q0 - WINDOW + 1) >> 6;
    const int kt_hi = (q0 + 127) >> 6;

    // prologue KV load
    {
        const size_t kb = (kvhead + (size_t)kt_lo * 64) * HD;
        uint32_t B0 = S0 + 65536;
#pragma unroll
        for (int p = 0; p < 4; p++) {
            int u = tid + (p << 8);
            int r = u >> 4, c = u & 15;
            uint32_t off = r * 256 + (uint32_t)((c ^ (r & 7)) << 4);
            size_t go = (size_t)r * 256 + c * 16;
            cp16(B0 + off, (const char*)(Kh + kb) + go);
            cp16(B0 + 16384 + off, (const char*)(Kl + kb) + go);
            cp16(B0 + 32768 + off, (const char*)(Vh + kb) + go);
            cp16(B0 + 49152 + off, (const char*)(Vl + kb) + go);
        }
    }
    cp_commit();

    float acc[16][4];
#pragma unroll
    for (int i = 0; i < 16; i++)
#pragma unroll
        for (int j = 0; j < 4; j++) acc[i][j] = 0.f;
    float m_run0 = NEG_INF_F, m_run1 = NEG_INF_F, l_run0 = 0.f, l_run1 = 0.f;

    const int r0g = q0 + m0 + (lane >> 2);  // global q index (row 0 of fragment)
    const int r1g = r0g + 8;
    const float ez = 2.0f * 0.08838834764831845f / 50.0f;

    // lane geometry
    const int a_r = lane & 15;
    const int a_ch = lane >> 4;
    const int sb_r = (lane & 7) + ((lane & 16) >> 1);   // scores B row offset
    const int sb_c = (lane >> 3) & 1;                    // scores B k-half
    const int pv_r = (lane & 7) + (lane & 8);            // PV B kv-row offset
    const int pv_c = (lane & 16) >> 4;                   // PV B d-chunk offset

    for (int kt = kt_lo; kt <= kt_hi; kt++) {
        const int buf = (kt - kt_lo) & 1;
        if (kt < kt_hi) {
            const size_t kb = (kvhead + (size_t)(kt + 1) * 64) * HD;
            uint32_t NB = S0 + 65536 + (buf ^ 1) * 65536;
#pragma unroll
            for (int p = 0; p < 4; p++) {
                int u = tid + (p << 8);
                int r = u >> 4, c = u & 15;
                uint32_t off = r * 256 + (uint32_t)((c ^ (r & 7)) << 4);
                size_t go = (size_t)r * 256 + c * 16;
                cp16(NB + off, (const char*)(Kh + kb) + go);
                cp16(NB + 16384 + off, (const char*)(Kl + kb) + go);
                cp16(NB + 32768 + off, (const char*)(Vh + kb) + go);
                cp16(NB + 49152 + off, (const char*)(Vl + kb) + go);
            }
            cp_commit();
            cp_wait1();
        } else {
            cp_wait0();
        }
        __syncthreads();

        const uint32_t KB = S0 + 65536 + buf * 65536;

        // ---- scores S = Q K^T (3-term split) ----
        float S[8][4];
#pragma unroll
        for (int i = 0; i < 8; i++)
#pragma unroll
            for (int j = 0; j < 4; j++) S[i][j] = 0.f;

#pragma unroll
        for (int kc = 0; kc < 8; kc++) {
            uint32_t aH[4], aL[4];
            {
                int r = m0 + a_r;
                uint32_t cl = (uint32_t)((2 * kc + a_ch) ^ (r & 7)) << 4;
                uint32_t ad = S0 + r * 256 + cl;
                LDSM4(aH[0], aH[1], aH[2], aH[3], ad);
                LDSM4(aL[0], aL[1], aL[2], aL[3], ad + 32768);
            }
#pragma unroll
            for (int np = 0; np < 4; np++) {
                int rr = np * 16 + sb_r;
                uint32_t cl = (uint32_t)((2 * kc + sb_c) ^ (rr & 7)) << 4;
                uint32_t bd = KB + rr * 256 + cl;
                uint32_t bh0, bh1, bh2, bh3, bl0, bl1, bl2, bl3;
                LDSM4(bh0, bh1, bh2, bh3, bd);
                LDSM4(bl0, bl1, bl2, bl3, bd + 16384);
                mma16816(S[2 * np], aH, bh0, bh1);
                mma16816(S[2 * np], aH, bl0, bl1);
                mma16816(S[2 * np], aL, bh0, bh1);
                mma16816(S[2 * np + 1], aH, bh2, bh3);
                mma16816(S[2 * np + 1], aH, bl2, bl3);
                mma16816(S[2 * np + 1], aL, bh2, bh3);
            }
        }

        // ---- tanh cap + mask + online softmax ----
        const int k0g = kt * 64;
        float mx0 = NEG_INF_F, mx1 = NEG_INF_F;
#pragma unroll
        for (int a = 0; a < 8; a++) {
            int cb = k0g + 8 * a + ((lane & 3) << 1);
            float t0 = __expf(ez * S[a][0]);
            float t1 = __expf(ez * S[a][1]);
            float t2 = __expf(ez * S[a][2]);
            float t3 = __expf(ez * S[a][3]);
            float v0 = 50.f * (1.f - __fdividef(2.f, t0 + 1.f));
            float v1 = 50.f * (1.f - __fdividef(2.f, t1 + 1.f));
            float v2 = 50.f * (1.f - __fdividef(2.f, t2 + 1.f));
            float v3 = 50.f * (1.f - __fdividef(2.f, t3 + 1.f));
            bool m00 = (cb <= r0g) && (cb > r0g - WINDOW);
            bool m01 = (cb + 1 <= r0g) && (cb + 1 > r0g - WINDOW);
            bool m10 = (cb <= r1g) && (cb > r1g - WINDOW);
            bool m11 = (cb + 1 <= r1g) && (cb + 1 > r1g - WINDOW);
            S[a][0] = m00 ? v0 : NEG_INF_F;
            S[a][1] = m01 ? v1 : NEG_INF_F;
            S[a][2] = m10 ? v2 : NEG_INF_F;
            S[a][3] = m11 ? v3 : NEG_INF_F;
            mx0 = fmaxf(mx0, fmaxf(S[a][0], S[a][1]));
            mx1 = fmaxf(mx1, fmaxf(S[a][2], S[a][3]));
        }
        mx0 = fmaxf(mx0, __shfl_xor_sync(~0u, mx0, 1));
        mx0 = fmaxf(mx0, __shfl_xor_sync(~0u, mx0, 2));
        mx1 = fmaxf(mx1, __shfl_xor_sync(~0u, mx1, 1));
        mx1 = fmaxf(mx1, __shfl_xor_sync(~0u, mx1, 2));

        float mn0 = fmaxf(m_run0, mx0), mn1 = fmaxf(m_run1, mx1);
        float cor0 = __expf(m_run0 - mn0), cor1 = __expf(m_run1 - mn1);
        float sum0 = 0.f, sum1 = 0.f;
#pragma unroll
        for (int a = 0; a < 8; a++) {
            float p0 = (S[a][0] > -1e29f) ? __expf(S[a][0] - mn0) : 0.f;
            float p1 = (S[a][1] > -1e29f) ? __expf(S[a][1] - mn0) : 0.f;
            float p2 = (S[a][2] > -1e29f) ? __expf(S[a][2] - mn1) : 0.f;
            float p3 = (S[a][3] > -1e29f) ? __expf(S[a][3] - mn1) : 0.f;
            S[a][0] = p0; S[a][1] = p1; S[a][2] = p2; S[a][3] = p3;
            sum0 += p0 + p1;
            sum1 += p2 + p3;
        }
        sum0 += __shfl_xor_sync(~0u, sum0, 1);
        sum0 += __shfl_xor_sync(~0u, sum0, 2);
        sum1 += __shfl_xor_sync(~0u, sum1, 1);
        sum1 += __shfl_xor_sync(~0u, sum1, 2);
        l_run0 = l_run0 * cor0 + sum0;
        l_run1 = l_run1 * cor1 + sum1;
        m_run0 = mn0;
        m_run1 = mn1;
#pragma unroll
        for (int i = 0; i < 16; i++) {
            acc[i][0] *= cor0; acc[i][1] *= cor0;
            acc[i][2] *= cor1; acc[i][3] *= cor1;
        }

        // ---- pack P into A fragments (hi/lo) ----
        uint32_t pH[4][4], pL[4][4];
#pragma unroll
        for (int j = 0; j < 4; j++) {
#pragma unroll
            for (int e = 0; e < 2; e++) {  // e=0: atom 2j (k0-7), e=1: atom 2j+1 (k8-15)
                int a = 2 * j + e;
                __nv_bfloat16 h0, l0, h1, l1, h2, l2, h3, l3;
                split2(S[a][0], h0, l0); split2(S[a][1], h1, l1);
                split2(S[a][2], h2, l2); split2(S[a][3], h3, l3);
                __nv_bfloat162 t;
                t.x = h0; t.y = h1; pH[j][0 + 2 * e] = *(uint32_t*)&t;
                t.x = h2; t.y = h3; pH[j][1 + 2 * e] = *(uint32_t*)&t;
                t.x = l0; t.y = l1; pL[j][0 + 2 * e] = *(uint32_t*)&t;
                t.x = l2; t.y = l3; pL[j][1 + 2 * e] = *(uint32_t*)&t;
            }
        }

        // ---- O += P V (3-term split), B via ldmatrix.trans ----
        const uint32_t VB = KB + 32768;
#pragma unroll
        for (int j = 0; j < 4; j++) {
            int kr = j * 16 + pv_r;
#pragma unroll
            for (int dp = 0; dp < 8; dp++) {
                uint32_t cch = (uint32_t)(2 * dp + pv_c);
                uint32_t addr = VB + kr * 256 + (((cch ^ (kr & 7))) << 4);
                uint32_t bh0, bh1, bh2, bh3, bl0, bl1, bl2, bl3;
                LDSM4T(bh0, bh1, bh2, bh3, addr);
                LDSM4T(bl0, bl1, bl2, bl3, addr + 16384);
                mma16816(acc[2 * dp], pH[j], bh0, bh1);
                mma16816(acc[2 * dp], pH[j], bl0, bl1);
                mma16816(acc[2 * dp], pL[j], bh0, bh1);
                mma16816(acc[2 * dp + 1], pH[j], bh2, bh3);
                mma16816(acc[2 * dp + 1], pH[j], bl2, bl3);
                mma16816(acc[2 * dp + 1], pL[j], bh2, bh3);
            }
        }
        __syncthreads();
    }

    // ---- epilogue: normalize, split, store [b*S+s][h*128+d] ----
    const float inv0 = 1.f / l_run0, inv1 = 1.f / l_run1;
    const size_t gr0 = (size_t)b * SEQ + q0 + m0 + (lane >> 2);
    const size_t gr1 = gr0 + 8;
    const int colb = h * HD + ((lane & 3) << 1);
#pragma unroll
    for (int nd = 0; nd < 16; nd++) {
        int col = colb + nd * 8;
        float a0 = acc[nd][0] * inv0, a1 = acc[nd][1] * inv0;
        float a2 = acc[nd][2] * inv1, a3 = acc[nd][3] * inv1;
        __nv_bfloat16 h0, l0, h1, l1;
        split2(a0, h0, l0); split2(a1, h1, l1);
        __nv_bfloat162 hh; hh.x = h0; hh.y = h1;
        __nv_bfloat162 ll; ll.x = l0; ll.y = l1;
        *(__nv_bfloat162*)(Oh + gr0 * NQ + col) = hh;
        *(__nv_bfloat162*)(Ol + gr0 * NQ + col) = ll;
        split2(a2, h0, l0); split2(a3, h1, l1);
        hh.x = h0; hh.y = h1; ll.x = l0; ll.y = l1;
        *(__nv_bfloat162*)(Oh + gr1 * NQ + col) = hh;
        *(__nv_bfloat162*)(Ol + gr1 * NQ + col) = ll;
    }
}

// ---------------- launch ----------------
extern "C" void kernel_launch(void* const* d_in, const int* in_sizes, int n_in,
                              void* d_out, int out_size) {
    const float* x = (const float*)d_in[0];
    const float* gamma = (const float*)d_in[1];
    const float* Wq = (const float*)d_in[2];
    const float* Wk = (const float*)d_in[3];
    const float* Wv = (const float*)d_in[4];
    const float* Wo = (const float*)d_in[5];
    float* out = (float*)d_out;

    __nv_bfloat16 *xnh, *xnl, *wqh, *wql, *wkh, *wkl, *wvh, *wvl, *woh, *wol, *ath, *atl;
    __nv_bfloat16 *qh, *ql, *kh, *kl, *vh, *vl;
    float *q, *k, *v, *cosT, *sinT;
    cudaGetSymbolAddress((void**)&xnh, g_xn_h);
    cudaGetSymbolAddress((void**)&xnl, g_xn_l);
    cudaGetSymbolAddress((void**)&wqh, g_wqT_h);
    cudaGetSymbolAddress((void**)&wql, g_wqT_l);
    cudaGetSymbolAddress((void**)&wkh, g_wkT_h);
    cudaGetSymbolAddress((void**)&wkl, g_wkT_l);
    cudaGetSymbolAddress((void**)&wvh, g_wvT_h);
    cudaGetSymbolAddress((void**)&wvl, g_wvT_l);
    cudaGetSymbolAddress((void**)&woh, g_woT_h);
    cudaGetSymbolAddress((void**)&wol, g_woT_l);
    cudaGetSymbolAddress((void**)&ath, g_at_h);
    cudaGetSymbolAddress((void**)&atl, g_at_l);
    cudaGetSymbolAddress((void**)&qh, g_qh);
    cudaGetSymbolAddress((void**)&ql, g_ql);
    cudaGetSymbolAddress((void**)&kh, g_kh);
    cudaGetSymbolAddress((void**)&kl, g_kl);
    cudaGetSymbolAddress((void**)&vh, g_vh);
    cudaGetSymbolAddress((void**)&vl, g_vl);
    cudaGetSymbolAddress((void**)&q, g_q);
    cudaGetSymbolAddress((void**)&k, g_k);
    cudaGetSymbolAddress((void**)&v, g_v);
    cudaGetSymbolAddress((void**)&cosT, g_cos);
    cudaGetSymbolAddress((void**)&sinT, g_sin);

    cudaFuncSetAttribute(gemm_mma, cudaFuncAttributeMaxDynamicSharedMemorySize, GEMM_SMEM);
    cudaFuncSetAttribute(attn_mma, cudaFuncAttributeMaxDynamicSharedMemorySize, AT_SMEM);

    // 1) RMSNorm -> split
    rmsnorm_kernel<<<MROWS, 256>>>(x, gamma, xnh, xnl);

    // 2) RoPE tables
    rope_table_kernel<<<(SEQ * 64 + 255) / 256, 256>>>(cosT, sinT);

    // 3) weight transpose + split
    {
        dim3 gq(HIDDEN / 64, NQ / 64);
        tsplit_kernel<<<gq, 256>>>(Wq, wqh, wql, HIDDEN, NQ);
        dim3 gk(HIDDEN / 64, NKV / 64);
        tsplit_kernel<<<gk, 256>>>(Wk, wkh, wkl, HIDDEN, NKV);
        tsplit_kernel<<<gk, 256>>>(Wv, wvh, wvl, HIDDEN, NKV);
        dim3 go(NQ / 64, HIDDEN / 64);
        tsplit_kernel<<<go, 256>>>(Wo, woh, wol, NQ, HIDDEN);
    }

    // 4) QKV projections
    {
        dim3 gq(NQ / 128, MROWS / 128);
        gemm_mma<<<gq, 256, GEMM_SMEM>>>(xnh, xnl, wqh, wql, (const float*)0, q, MROWS, NQ, HIDDEN);
        dim3 gk(NKV / 128, MROWS / 128);
        gemm_mma<<<gk, 256, GEMM_SMEM>>>(xnh, xnl, wkh, wkl, (const float*)0, k, MROWS, NKV, HIDDEN);
        gemm_mma<<<gk, 256, GEMM_SMEM>>>(xnh, xnl, wvh, wvl, (const float*)0, v, MROWS, NKV, HIDDEN);
    }

    // 5) RoPE + transpose + split
    {
        long tq = (long)BATCH * HQ * SEQ * 64;
        rope_split_kernel<<<(int)((tq + 255) / 256), 256>>>(q, qh, ql, HQ, tq);
        long tk = (long)BATCH * HKV * SEQ * 64;
        rope_split_kernel<<<(int)((tk + 255) / 256), 256>>>(k, kh, kl, HKV, tk);
        long tv = (long)BATCH * HKV * SEQ * 128;
        vsplit_kernel<<<(int)((tv + 255) / 256), 256>>>(v, vh, vl, tv);
    }

    // 6) attention (tensor cores)
    {
        dim3 ga(SEQ / 128, HQ, BATCH);
        attn_mma<<<ga, 256, AT_SMEM>>>(qh, ql, kh, kl, vh, vl, ath, atl);
    }

    // 7) output projection + residual
    {
        dim3 go(HIDDEN / 128, MROWS / 128);
        gemm_mma<<<go, 256, GEMM_SMEM>>>(ath, atl, woh, wol, x, out, MROWS, HIDDEN, NQ);
    }
}

// round 6
// speedup vs baseline: 7.2935x; 1.4078x over previous
#include <cuda_runtime.h>
#include <cuda_fp16.h>
#include <math.h>
#include <stdint.h>

#define SEQ 2048
#define BATCH 2
#define HIDDEN 4096
#define HD 128
#define HQ 32
#define HKV 8
#define WINDOW 1024
#define NEG_INF_F (-1e30f)
#define MROWS (BATCH * SEQ) /* 4096 */
#define NQ (HQ * HD)        /* 4096 */
#define NKV (HKV * HD)      /* 1024 */

// ---------------- scratch (static device arrays; no allocations) ----------------
__device__ __half g_xn_h[(size_t)MROWS * HIDDEN];
__device__ __half g_wqT_h[(size_t)NQ * HIDDEN];
__device__ __half g_wqT_l[(size_t)NQ * HIDDEN];
__device__ __half g_wkT_h[(size_t)NKV * HIDDEN];
__device__ __half g_wkT_l[(size_t)NKV * HIDDEN];
__device__ __half g_wvT_h[(size_t)NKV * HIDDEN];
__device__ __half g_wvT_l[(size_t)NKV * HIDDEN];
__device__ __half g_woT_h[(size_t)HIDDEN * NQ];
__device__ __half g_woT_l[(size_t)HIDDEN * NQ];
__device__ float g_q[(size_t)MROWS * NQ];
__device__ float g_k[(size_t)MROWS * NKV];
__device__ float g_v[(size_t)MROWS * NKV];
// head-major fp16 for attention
__device__ __half g_qh[(size_t)BATCH * HQ * SEQ * HD];
__device__ __half g_kh[(size_t)BATCH * HKV * SEQ * HD];
__device__ __half g_kl[(size_t)BATCH * HKV * SEQ * HD];
__device__ __half g_vh[(size_t)BATCH * HKV * SEQ * HD];
__device__ __half g_vl[(size_t)BATCH * HKV * SEQ * HD];
__device__ __half g_at_h[(size_t)MROWS * NQ];
__device__ float g_cos[SEQ * 64];
__device__ float g_sin[SEQ * 64];

// ---------------- PTX helpers (baseline sm_80+ ISA only) ----------------
__device__ __forceinline__ uint32_t smem_u32(const void* p) {
    uint32_t a;
    asm("{ .reg .u64 t; cvta.to.shared.u64 t, %1; cvt.u32.u64 %0, t; }" : "=r"(a) : "l"(p));
    return a;
}
__device__ __forceinline__ void cp16(uint32_t s, const void* g) {
    asm volatile("cp.async.cg.shared.global [%0], [%1], 16;" :: "r"(s), "l"(g));
}
__device__ __forceinline__ void cp_commit() {
    asm volatile("cp.async.commit_group;" ::: "memory");
}
__device__ __forceinline__ void cp_wait0() {
    asm volatile("cp.async.wait_group 0;" ::: "memory");
}
__device__ __forceinline__ void cp_wait1() {
    asm volatile("cp.async.wait_group 1;" ::: "memory");
}
#define LDSM4(r0, r1, r2, r3, a) \
    asm volatile("ldmatrix.sync.aligned.m8n8.x4.shared.b16 {%0,%1,%2,%3}, [%4];" \
                 : "=r"(r0), "=r"(r1), "=r"(r2), "=r"(r3) : "r"(a))
#define LDSM4T(r0, r1, r2, r3, a) \
    asm volatile("ldmatrix.sync.aligned.m8n8.x4.trans.shared.b16 {%0,%1,%2,%3}, [%4];" \
                 : "=r"(r0), "=r"(r1), "=r"(r2), "=r"(r3) : "r"(a))

__device__ __forceinline__ void mma16816(float* d, const uint32_t* a, uint32_t b0, uint32_t b1) {
    asm volatile(
        "mma.sync.aligned.m16n8k16.row.col.f32.f16.f16.f32 "
        "{%0,%1,%2,%3}, {%4,%5,%6,%7}, {%8,%9}, {%0,%1,%2,%3};"
        : "+f"(d[0]), "+f"(d[1]), "+f"(d[2]), "+f"(d[3])
        : "r"(a[0]), "r"(a[1]), "r"(a[2]), "r"(a[3]), "r"(b0), "r"(b1));
}

__device__ __forceinline__ void split2h(float x, __half& h, __half& l) {
    h = __float2half_rn(x);
    l = __float2half_rn(x - __half2float(h));
}
__device__ __forceinline__ uint32_t pk2(float a, float b) {
    __half2 t;
    t.x = __float2half_rn(a);
    t.y = __float2half_rn(b);
    return *(uint32_t*)&t;
}

// ---------------- RMSNorm -> fp16 (single) ----------------
__global__ __launch_bounds__(256) void rmsnorm_kernel(
    const float* __restrict__ x, const float* __restrict__ gamma,
    __half* __restrict__ xh) {
    const int row = blockIdx.x;
    const float4* xr = (const float4*)(x + (size_t)row * HIDDEN);
    const float4* g4 = (const float4*)gamma;

    float ss = 0.f;
    float4 v[4];
#pragma unroll
    for (int i = 0; i < 4; i++) {
        v[i] = xr[threadIdx.x + 256 * i];
        ss += v[i].x * v[i].x + v[i].y * v[i].y + v[i].z * v[i].z + v[i].w * v[i].w;
    }
#pragma unroll
    for (int o = 16; o > 0; o >>= 1) ss += __shfl_xor_sync(~0u, ss, o);
    __shared__ float sred[8];
    if ((threadIdx.x & 31) == 0) sred[threadIdx.x >> 5] = ss;
    __syncthreads();
    float tot = 0.f;
#pragma unroll
    for (int i = 0; i < 8; i++) tot += sred[i];

    const float inv = rsqrtf(tot / (float)HIDDEN + 1e-5f);
    size_t rb = (size_t)row * HIDDEN;
#pragma unroll
    for (int i = 0; i < 4; i++) {
        float4 g = g4[threadIdx.x + 256 * i];
        size_t e = rb + (size_t)(threadIdx.x + 256 * i) * 4;
        __half2 h01, h23;
        h01.x = __float2half_rn(v[i].x * inv * g.x);
        h01.y = __float2half_rn(v[i].y * inv * g.y);
        h23.x = __float2half_rn(v[i].z * inv * g.z);
        h23.y = __float2half_rn(v[i].w * inv * g.w);
        *(__half2*)(xh + e) = h01;
        *(__half2*)(xh + e + 2) = h23;
    }
}

// ---------------- weight transpose + split: W[K,N] -> T[N,K] fp16 hi/lo ----------------
__global__ __launch_bounds__(256) void tsplit_kernel(
    const float* __restrict__ W, __half* __restrict__ Th,
    __half* __restrict__ Tl, int K, int N) {
    __shared__ __half sh[64][68];
    __shared__ __half sl[64][68];
    const int k0 = blockIdx.x * 64, n0 = blockIdx.y * 64;
    const int tid = threadIdx.x;

    for (int i = tid; i < 64 * 16; i += 256) {
        int r = i >> 4;
        int c4 = (i & 15) << 2;
        float4 w = *(const float4*)&W[(size_t)(k0 + r) * N + n0 + c4];
        split2h(w.x, sh[c4 + 0][r], sl[c4 + 0][r]);
        split2h(w.y, sh[c4 + 1][r], sl[c4 + 1][r]);
        split2h(w.z, sh[c4 + 2][r], sl[c4 + 2][r]);
        split2h(w.w, sh[c4 + 3][r], sl[c4 + 3][r]);
    }
    __syncthreads();
    for (int i = tid; i < 64 * 32; i += 256) {
        int n = i >> 5, kk2 = (i & 31) << 1;
        size_t off = (size_t)(n0 + n) * K + k0 + kk2;
        __half2 h; h.x = sh[n][kk2]; h.y = sh[n][kk2 + 1];
        __half2 l; l.x = sl[n][kk2]; l.y = sl[n][kk2 + 1];
        *(__half2*)(Th + off) = h;
        *(__half2*)(Tl + off) = l;
    }
}

// ---------------- mma.sync GEMM: C = A(fp16) @ T(fp16 hi/lo)^T (+R), 2-term ----------------
// Tile 128x128, BK=64; smem/buffer 48KB (A 16K | Bh 16K | Bl 16K); double-buffered; 2 CTAs/SM.
#define GEMM_SMEM (2 * 49152)

__device__ __forceinline__ void load_sub(uint32_t sdst, const __half* src,
                                         int rbase, int K, int k0, int tid) {
#pragma unroll
    for (int p = 0; p < 4; p++) {
        int u = tid + (p << 8);
        int r = u >> 3, c16 = u & 7;
        const char* g = (const char*)(src + (size_t)(rbase + r) * K + k0) + (c16 << 4);
        cp16(sdst + r * 128 + ((c16 ^ (r & 7)) << 4), g);
    }
}

__global__ __launch_bounds__(256, 2) void gemm_mma(
    const __half* __restrict__ Ah,
    const __half* __restrict__ Bh, const __half* __restrict__ Bl,
    const float* __restrict__ R, float* __restrict__ C, int M, int N, int K) {
    extern __shared__ char smraw[];
    const uint32_t sbase = smem_u32(smraw);
    const int tid = threadIdx.x;
    const int lane = tid & 31, wid = tid >> 5;
    const int row0 = blockIdx.y * 128, col0 = blockIdx.x * 128;
    const int wm = (wid & 1) * 64, wn = (wid >> 1) * 32;

    float acc[4][4][4];
#pragma unroll
    for (int i = 0; i < 4; i++)
#pragma unroll
        for (int j = 0; j < 4; j++)
#pragma unroll
            for (int r = 0; r < 4; r++) acc[i][j][r] = 0.f;

    const int NC = K >> 6;

    load_sub(sbase,         Ah, row0, K, 0, tid);
    load_sub(sbase + 16384, Bh, col0, K, 0, tid);
    load_sub(sbase + 32768, Bl, col0, K, 0, tid);
    cp_commit();

    const int a_r = lane & 15;
    const int a_ch = lane >> 4;
    const int b_n = ((lane >> 4) << 3) + (lane & 7);
    const int b_kh = (lane >> 3) & 1;

    for (int c = 0; c < NC; c++) {
        const int buf = c & 1;
        if (c + 1 < NC) {
            const uint32_t nb = sbase + (buf ^ 1) * 49152;
            const int k0 = (c + 1) << 6;
            load_sub(nb,         Ah, row0, K, k0, tid);
            load_sub(nb + 16384, Bh, col0, K, k0, tid);
            load_sub(nb + 32768, Bl, col0, K, k0, tid);
            cp_commit();
            cp_wait1();
        } else {
            cp_wait0();
        }
        __syncthreads();

        const uint32_t sb = sbase + buf * 49152;
#pragma unroll
        for (int ks = 0; ks < 4; ks++) {
            uint32_t aH[4][4], bH[2][4], bL[2][4];
#pragma unroll
            for (int i = 0; i < 4; i++) {
                int r = wm + i * 16 + a_r;
                uint32_t cl = (uint32_t)((ks * 2 + a_ch) ^ (r & 7)) << 4;
                LDSM4(aH[i][0], aH[i][1], aH[i][2], aH[i][3], sb + r * 128 + cl);
            }
#pragma unroll
            for (int j = 0; j < 2; j++) {
                int r = wn + j * 16 + b_n;
                uint32_t cl = (uint32_t)((ks * 2 + b_kh) ^ (r & 7)) << 4;
                uint32_t bd = sb + 16384 + r * 128 + cl;
                LDSM4(bH[j][0], bH[j][1], bH[j][2], bH[j][3], bd);
                LDSM4(bL[j][0], bL[j][1], bL[j][2], bL[j][3], bd + 16384);
            }
#pragma unroll
            for (int i = 0; i < 4; i++) {
#pragma unroll
                for (int jn = 0; jn < 4; jn++) {
                    uint32_t h0 = bH[jn >> 1][(jn & 1) * 2], h1 = bH[jn >> 1][(jn & 1) * 2 + 1];
                    uint32_t l0 = bL[jn >> 1][(jn & 1) * 2], l1 = bL[jn >> 1][(jn & 1) * 2 + 1];
                    mma16816(acc[i][jn], aH[i], h0, h1);
                    mma16816(acc[i][jn], aH[i], l0, l1);
                }
            }
        }
        __syncthreads();
    }

    const int mrow = lane >> 2, ncol = (lane & 3) * 2;
#pragma unroll
    for (int i = 0; i < 4; i++) {
        int gr = row0 + wm + i * 16 + mrow;
#pragma unroll
        for (int jn = 0; jn < 4; jn++) {
            int gc = col0 + wn + jn * 8 + ncol;
            float2 v0 = make_float2(acc[i][jn][0], acc[i][jn][1]);
            float2 v1 = make_float2(acc[i][jn][2], acc[i][jn][3]);
            if (R) {
                float2 r0 = *(const float2*)&R[(size_t)gr * N + gc];
                float2 r1 = *(const float2*)&R[(size_t)(gr + 8) * N + gc];
                v0.x += r0.x; v0.y += r0.y;
                v1.x += r1.x; v1.y += r1.y;
            }
            *(float2*)&C[(size_t)gr * N + gc] = v0;
            *(float2*)&C[(size_t)(gr + 8) * N + gc] = v1;
        }
    }
}

// ---------------- RoPE tables ----------------
__global__ void rope_table_kernel(float* __restrict__ cosT, float* __restrict__ sinT) {
    int idx = blockIdx.x * blockDim.x + threadIdx.x;
    if (idx >= SEQ * 64) return;
    int s = idx >> 6, i = idx & 63;
    double ang = (double)s * pow(10000.0, -(double)i / 64.0);
    double sn, cs;
    sincos(ang, &sn, &cs);
    cosT[idx] = (float)cs;
    sinT[idx] = (float)sn;
}

// ---------------- RoPE + transpose head-major + fp16 (optional lo) ----------------
__global__ __launch_bounds__(256) void rope_split_kernel(
    const float* __restrict__ src, __half* __restrict__ dh,
    __half* __restrict__ dl, int nheads, long total) {
    long idx = (long)blockIdx.x * blockDim.x + threadIdx.x;
    if (idx >= total) return;
    int i = (int)(idx & 63);
    long t = idx >> 6;
    int s = (int)(t & (SEQ - 1));
    t >>= 11;
    int h = (int)(t % nheads);
    int b = (int)(t / nheads);
    const float* sp = src + ((size_t)b * SEQ + s) * (size_t)(nheads * HD) + (size_t)h * HD;
    float a = sp[i], bb = sp[i + 64];
    float c = g_cos[s * 64 + i], sn = g_sin[s * 64 + i];
    float o1 = a * c - bb * sn;
    float o2 = bb * c + a * sn;
    size_t d = (((size_t)b * nheads + h) * SEQ + s) * HD;
    if (dl) {
        __half h1, l1, h2, l2;
        split2h(o1, h1, l1); split2h(o2, h2, l2);
        dh[d + i] = h1; dl[d + i] = l1;
        dh[d + i + 64] = h2; dl[d + i + 64] = l2;
    } else {
        dh[d + i] = __float2half_rn(o1);
        dh[d + i + 64] = __float2half_rn(o2);
    }
}

// ---------------- V transpose head-major + fp16 hi/lo ----------------
__global__ __launch_bounds__(256) void vsplit_kernel(
    const float* __restrict__ src, __half* __restrict__ dh,
    __half* __restrict__ dl, long total) {
    long idx = (long)blockIdx.x * blockDim.x + threadIdx.x;
    if (idx >= total) return;
    int i = (int)(idx & 127);
    long t = idx >> 7;
    int s = (int)(t & (SEQ - 1));
    t >>= 11;
    int h = (int)(t % HKV);
    int b = (int)(t / HKV);
    float v = src[((size_t)b * SEQ + s) * NKV + (size_t)h * HD + i];
    size_t d = (((size_t)b * HKV + h) * SEQ + s) * HD + i;
    __half hh, ll;
    split2h(v, hh, ll);
    dh[d] = hh;
    dl[d] = ll;
}

// ---------------- attention via mma.sync (fp16 2-term) ----------------
// grid (SEQ/128, HQ, B), 256 threads. smem: Q 32K | 2x{Kh|Kl|Vh|Vl 16K each} = 160KB
#define AT_SMEM (163840)

__global__ __launch_bounds__(256) void attn_mma(
    const __half* __restrict__ Qh,
    const __half* __restrict__ Kh, const __half* __restrict__ Kl,
    const __half* __restrict__ Vh, const __half* __restrict__ Vl,
    __half* __restrict__ Oh) {
    extern __shared__ char smraw[];
    const uint32_t S0 = smem_u32(smraw);
    const int tid = threadIdx.x;
    const int lane = tid & 31, wid = tid >> 5;
    const int qt = blockIdx.x, h = blockIdx.y, b = blockIdx.z;
    const int g = h >> 2;
    const int q0 = qt * 128;
    const int m0 = wid * 16;

    // ---- load Q into swizzled smem (256B rows) ----
    {
        const char* qb = (const char*)(Qh + (((size_t)b * HQ + h) * SEQ + q0) * HD);
#pragma unroll
        for (int p = 0; p < 8; p++) {
            int u = tid + (p << 8);
            int r = u >> 4, c = u & 15;
            cp16(S0 + r * 256 + (uint32_t)((c ^ (r & 7)) << 4), qb + r * 256 + c * 16);
        }
    }

    const size_t kvhead = ((size_t)b * HKV + g) * SEQ;
    const int kt_lo = max(0, q0 - WINDOW + 1) >> 6;
    const int kt_hi = (q0 + 127) >> 6;

    {
        const size_t kb = (kvhead + (size_t)kt_lo * 64) * HD;
        uint32_t B0 = S0 + 32768;
#pragma unroll
        for (int p = 0; p < 4; p++) {
            int u = tid + (p << 8);
            int r = u >> 4, c = u & 15;
            uint32_t off = r * 256 + (uint32_t)((c ^ (r & 7)) << 4);
            size_t go = (size_t)r * 256 + c * 16;
            cp16(B0 + off, (const char*)(Kh + kb) + go);
            cp16(B0 + 16384 + off, (const char*)(Kl + kb) + go);
            cp16(B0 + 32768 + off, (const char*)(Vh + kb) + go);
            cp16(B0 + 49152 + off, (const char*)(Vl + kb) + go);
        }
    }
    cp_commit();

    float acc[16][4];
#pragma unroll
    for (int i = 0; i < 16; i++)
#pragma unroll
        for (int j = 0; j < 4; j++) acc[i][j] = 0.f;
    float m_run0 = NEG_INF_F, m_run1 = NEG_INF_F, l_run0 = 0.f, l_run1 = 0.f;

    const int r0g = q0 + m0 + (lane >> 2);
    const int r1g = r0g + 8;
    const float ez = 2.0f * 0.08838834764831845f / 50.0f;

    const int a_r = lane & 15;
    const int a_ch = lane >> 4;
    const int sb_r = (lane & 7) + ((lane & 16) >> 1);
    const int sb_c = (lane >> 3) & 1;
    const int pv_r = (lane & 7) + (lane & 8);
    const int pv_c = (lane & 16) >> 4;

    for (int kt = kt_lo; kt <= kt_hi; kt++) {
        const int buf = (kt - kt_lo) & 1;
        if (kt < kt_hi) {
            const size_t kb = (kvhead + (size_t)(kt + 1) * 64) * HD;
            uint32_t NB = S0 + 32768 + (buf ^ 1) * 65536;
#pragma unroll
            for (int p = 0; p < 4; p++) {
                int u = tid + (p << 8);
                int r = u >> 4, c = u & 15;
                uint32_t off = r * 256 + (uint32_t)((c ^ (r & 7)) << 4);
                size_t go = (size_t)r * 256 + c * 16;
                cp16(NB + off, (const char*)(Kh + kb) + go);
                cp16(NB + 16384 + off, (const char*)(Kl + kb) + go);
                cp16(NB + 32768 + off, (const char*)(Vh + kb) + go);
                cp16(NB + 49152 + off, (const char*)(Vl + kb) + go);
            }
            cp_commit();
            cp_wait1();
        } else {
            cp_wait0();
        }
        __syncthreads();

        const uint32_t KB = S0 + 32768 + buf * 65536;

        // ---- scores S = Q K^T (2-term) ----
        float S[8][4];
#pragma unroll
        for (int i = 0; i < 8; i++)
#pragma unroll
            for (int j = 0; j < 4; j++) S[i][j] = 0.f;

#pragma unroll
        for (int kc = 0; kc < 8; kc++) {
            uint32_t aH[4];
            {
                int r = m0 + a_r;
                uint32_t cl = (uint32_t)((2 * kc + a_ch) ^ (r & 7)) << 4;
                LDSM4(aH[0], aH[1], aH[2], aH[3], S0 + r * 256 + cl);
            }
#pragma unroll
            for (int np = 0; np < 4; np++) {
                int rr = np * 16 + sb_r;
                uint32_t cl = (uint32_t)((2 * kc + sb_c) ^ (rr & 7)) << 4;
                uint32_t bd = KB + rr * 256 + cl;
                uint32_t bh0, bh1, bh2, bh3, bl0, bl1, bl2, bl3;
                LDSM4(bh0, bh1, bh2, bh3, bd);
                LDSM4(bl0, bl1, bl2, bl3, bd + 16384);
                mma16816(S[2 * np], aH, bh0, bh1);
                mma16816(S[2 * np], aH, bl0, bl1);
                mma16816(S[2 * np + 1], aH, bh2, bh3);
                mma16816(S[2 * np + 1], aH, bl2, bl3);
            }
        }

        // ---- tanh cap + mask + online softmax ----
        const int k0g = kt * 64;
        float mx0 = NEG_INF_F, mx1 = NEG_INF_F;
#pragma unroll
        for (int a = 0; a < 8; a++) {
            int cb = k0g + 8 * a + ((lane & 3) << 1);
            float t0 = __expf(ez * S[a][0]);
            float t1 = __expf(ez * S[a][1]);
            float t2 = __expf(ez * S[a][2]);
            float t3 = __expf(ez * S[a][3]);
            float v0 = 50.f * (1.f - __fdividef(2.f, t0 + 1.f));
            float v1 = 50.f * (1.f - __fdividef(2.f, t1 + 1.f));
            float v2 = 50.f * (1.f - __fdividef(2.f, t2 + 1.f));
            float v3 = 50.f * (1.f - __fdividef(2.f, t3 + 1.f));
            bool m00 = (cb <= r0g) && (cb > r0g - WINDOW);
            bool m01 = (cb + 1 <= r0g) && (cb + 1 > r0g - WINDOW);
            bool m10 = (cb <= r1g) && (cb > r1g - WINDOW);
            bool m11 = (cb + 1 <= r1g) && (cb + 1 > r1g - WINDOW);
            S[a][0] = m00 ? v0 : NEG_INF_F;
            S[a][1] = m01 ? v1 : NEG_INF_F;
            S[a][2] = m10 ? v2 : NEG_INF_F;
            S[a][3] = m11 ? v3 : NEG_INF_F;
            mx0 = fmaxf(mx0, fmaxf(S[a][0], S[a][1]));
            mx1 = fmaxf(mx1, fmaxf(S[a][2], S[a][3]));
        }
        mx0 = fmaxf(mx0, __shfl_xor_sync(~0u, mx0, 1));
        mx0 = fmaxf(mx0, __shfl_xor_sync(~0u, mx0, 2));
        mx1 = fmaxf(mx1, __shfl_xor_sync(~0u, mx1, 1));
        mx1 = fmaxf(mx1, __shfl_xor_sync(~0u, mx1, 2));

        float mn0 = fmaxf(m_run0, mx0), mn1 = fmaxf(m_run1, mx1);
        float cor0 = __expf(m_run0 - mn0), cor1 = __expf(m_run1 - mn1);
        float sum0 = 0.f, sum1 = 0.f;
#pragma unroll
        for (int a = 0; a < 8; a++) {
            float p0 = (S[a][0] > -1e29f) ? __expf(S[a][0] - mn0) : 0.f;
            float p1 = (S[a][1] > -1e29f) ? __expf(S[a][1] - mn0) : 0.f;
            float p2 = (S[a][2] > -1e29f) ? __expf(S[a][2] - mn1) : 0.f;
            float p3 = (S[a][3] > -1e29f) ? __expf(S[a][3] - mn1) : 0.f;
            S[a][0] = p0; S[a][1] = p1; S[a][2] = p2; S[a][3] = p3;
            sum0 += p0 + p1;
            sum1 += p2 + p3;
        }
        sum0 += __shfl_xor_sync(~0u, sum0, 1);
        sum0 += __shfl_xor_sync(~0u, sum0, 2);
        sum1 += __shfl_xor_sync(~0u, sum1, 1);
        sum1 += __shfl_xor_sync(~0u, sum1, 2);
        l_run0 = l_run0 * cor0 + sum0;
        l_run1 = l_run1 * cor1 + sum1;
        m_run0 = mn0;
        m_run1 = mn1;
#pragma unroll
        for (int i = 0; i < 16; i++) {
            acc[i][0] *= cor0; acc[i][1] *= cor0;
            acc[i][2] *= cor1; acc[i][3] *= cor1;
        }

        // ---- pack P (fp16 single) ----
        uint32_t pH[4][4];
#pragma unroll
        for (int j = 0; j < 4; j++) {
#pragma unroll
            for (int e = 0; e < 2; e++) {
                int a = 2 * j + e;
                pH[j][0 + 2 * e] = pk2(S[a][0], S[a][1]);
                pH[j][1 + 2 * e] = pk2(S[a][2], S[a][3]);
            }
        }

        // ---- O += P V (2-term), V via ldmatrix.trans ----
        const uint32_t VB = KB + 32768;
#pragma unroll
        for (int j = 0; j < 4; j++) {
            int kr = j * 16 + pv_r;
#pragma unroll
            for (int dp = 0; dp < 8; dp++) {
                uint32_t cch = (uint32_t)(2 * dp + pv_c);
                uint32_t addr = VB + kr * 256 + (((cch ^ (kr & 7))) << 4);
                uint32_t bh0, bh1, bh2, bh3, bl0, bl1, bl2, bl3;
                LDSM4T(bh0, bh1, bh2, bh3, addr);
                LDSM4T(bl0, bl1, bl2, bl3, addr + 16384);
                mma16816(acc[2 * dp], pH[j], bh0, bh1);
                mma16816(acc[2 * dp], pH[j], bl0, bl1);
                mma16816(acc[2 * dp + 1], pH[j], bh2, bh3);
                mma16816(acc[2 * dp + 1], pH[j], bl2, bl3);
            }
        }
        __syncthreads();
    }

    // ---- epilogue: normalize -> fp16 single, layout [b*S+s][h*128+d] ----
    const float inv0 = 1.f / l_run0, inv1 = 1.f / l_run1;
    const size_t gr0 = (size_t)b * SEQ + q0 + m0 + (lane >> 2);
    const size_t gr1 = gr0 + 8;
    const int colb = h * HD + ((lane & 3) << 1);
#pragma unroll
    for (int nd = 0; nd < 16; nd++) {
        int col = colb + nd * 8;
        *(uint32_t*)(Oh + gr0 * NQ + col) = pk2(acc[nd][0] * inv0, acc[nd][1] * inv0);
        *(uint32_t*)(Oh + gr1 * NQ + col) = pk2(acc[nd][2] * inv1, acc[nd][3] * inv1);
    }
}

// ---------------- launch ----------------
extern "C" void kernel_launch(void* const* d_in, const int* in_sizes, int n_in,
                              void* d_out, int out_size) {
    const float* x = (const float*)d_in[0];
    const float* gamma = (const float*)d_in[1];
    const float* Wq = (const float*)d_in[2];
    const float* Wk = (const float*)d_in[3];
    const float* Wv = (const float*)d_in[4];
    const float* Wo = (const float*)d_in[5];
    float* out = (float*)d_out;

    __half *xnh, *wqh, *wql, *wkh, *wkl, *wvh, *wvl, *woh, *wol, *ath;
    __half *qh, *kh, *kl, *vh, *vl;
    float *q, *k, *v, *cosT, *sinT;
    cudaGetSymbolAddress((void**)&xnh, g_xn_h);
    cudaGetSymbolAddress((void**)&wqh, g_wqT_h);
    cudaGetSymbolAddress((void**)&wql, g_wqT_l);
    cudaGetSymbolAddress((void**)&wkh, g_wkT_h);
    cudaGetSymbolAddress((void**)&wkl, g_wkT_l);
    cudaGetSymbolAddress((void**)&wvh, g_wvT_h);
    cudaGetSymbolAddress((void**)&wvl, g_wvT_l);
    cudaGetSymbolAddress((void**)&woh, g_woT_h);
    cudaGetSymbolAddress((void**)&wol, g_woT_l);
    cudaGetSymbolAddress((void**)&ath, g_at_h);
    cudaGetSymbolAddress((void**)&qh, g_qh);
    cudaGetSymbolAddress((void**)&kh, g_kh);
    cudaGetSymbolAddress((void**)&kl, g_kl);
    cudaGetSymbolAddress((void**)&vh, g_vh);
    cudaGetSymbolAddress((void**)&vl, g_vl);
    cudaGetSymbolAddress((void**)&q, g_q);
    cudaGetSymbolAddress((void**)&k, g_k);
    cudaGetSymbolAddress((void**)&v, g_v);
    cudaGetSymbolAddress((void**)&cosT, g_cos);
    cudaGetSymbolAddress((void**)&sinT, g_sin);

    cudaFuncSetAttribute(gemm_mma, cudaFuncAttributeMaxDynamicSharedMemorySize, GEMM_SMEM);
    cudaFuncSetAttribute(attn_mma, cudaFuncAttributeMaxDynamicSharedMemorySize, AT_SMEM);

    // launches 1-4: weight splits (independent)
    {
        dim3 gq(HIDDEN / 64, NQ / 64);
        tsplit_kernel<<<gq, 256>>>(Wq, wqh, wql, HIDDEN, NQ);
        dim3 gk(HIDDEN / 64, NKV / 64);
        tsplit_kernel<<<gk, 256>>>(Wk, wkh, wkl, HIDDEN, NKV);
        tsplit_kernel<<<gk, 256>>>(Wv, wvh, wvl, HIDDEN, NKV);
        dim3 go(NQ / 64, HIDDEN / 64);
        tsplit_kernel<<<go, 256>>>(Wo, woh, wol, NQ, HIDDEN);
    }

    // launch 5: RMSNorm
    rmsnorm_kernel<<<MROWS, 256>>>(x, gamma, xnh);

    // launch 6: Wq GEMM  (this is the ncu-profiled launch: -s 5 -c 1)
    {
        dim3 gq(NQ / 128, MROWS / 128);
        gemm_mma<<<gq, 256, GEMM_SMEM>>>(xnh, wqh, wql, (const float*)0, q, MROWS, NQ, HIDDEN);
    }

    // launch 7: RoPE tables
    rope_table_kernel<<<(SEQ * 64 + 255) / 256, 256>>>(cosT, sinT);

    // launches 8-9: Wk, Wv GEMMs
    {
        dim3 gk(NKV / 128, MROWS / 128);
        gemm_mma<<<gk, 256, GEMM_SMEM>>>(xnh, wkh, wkl, (const float*)0, k, MROWS, NKV, HIDDEN);
        gemm_mma<<<gk, 256, GEMM_SMEM>>>(xnh, wvh, wvl, (const float*)0, v, MROWS, NKV, HIDDEN);
    }

    // launches 10-12: RoPE + transpose + split
    {
        long tq = (long)BATCH * HQ * SEQ * 64;
        rope_split_kernel<<<(int)((tq + 255) / 256), 256>>>(q, qh, (__half*)0, HQ, tq);
        long tk = (long)BATCH * HKV * SEQ * 64;
        rope_split_kernel<<<(int)((tk + 255) / 256), 256>>>(k, kh, kl, HKV, tk);
        long tv = (long)BATCH * HKV * SEQ * 128;
        vsplit_kernel<<<(int)((tv + 255) / 256), 256>>>(v, vh, vl, tv);
    }

    // launch 13: attention
    {
        dim3 ga(SEQ / 128, HQ, BATCH);
        attn_mma<<<ga, 256, AT_SMEM>>>(qh, kh, kl, vh, vl, ath);
    }

    // launch 14: output projection + residual
    {
        dim3 go(HIDDEN / 128, MROWS / 128);
        gemm_mma<<<go, 256, GEMM_SMEM>>>(ath, woh, wol, x, out, MROWS, HIDDEN, NQ);
    }
}

// round 8
// speedup vs baseline: 9.8401x; 1.3492x over previous
#include <cuda_runtime.h>
#include <cuda_fp16.h>
#include <math.h>
#include <stdint.h>

#define SEQ 2048
#define BATCH 2
#define HIDDEN 4096
#define HD 128
#define HQ 32
#define HKV 8
#define WINDOW 1024
#define NEG_INF_F (-1e30f)
#define MROWS (BATCH * SEQ) /* 4096 */
#define NQ (HQ * HD)        /* 4096 */
#define NKV (HKV * HD)      /* 1024 */

// ---------------- scratch (static device arrays; no allocations) ----------------
__device__ __half g_xn_h[(size_t)MROWS * HIDDEN];
__device__ __half g_wqT[(size_t)NQ * HIDDEN];
__device__ __half g_wkT[(size_t)NKV * HIDDEN];
__device__ __half g_wvT[(size_t)NKV * HIDDEN];
__device__ __half g_woT[(size_t)HIDDEN * NQ];
__device__ float g_q[(size_t)MROWS * NQ];
__device__ float g_k[(size_t)MROWS * NKV];
__device__ float g_v[(size_t)MROWS * NKV];
// head-major fp16 for attention
__device__ __half g_qh[(size_t)BATCH * HQ * SEQ * HD];
__device__ __half g_kh[(size_t)BATCH * HKV * SEQ * HD];
__device__ __half g_vh[(size_t)BATCH * HKV * SEQ * HD];
__device__ __half g_at_h[(size_t)MROWS * NQ];
__device__ float g_cos[SEQ * 64];
__device__ float g_sin[SEQ * 64];

// ---------------- PTX helpers (baseline sm_80+ ISA only) ----------------
__device__ __forceinline__ uint32_t smem_u32(const void* p) {
    uint32_t a;
    asm("{ .reg .u64 t; cvta.to.shared.u64 t, %1; cvt.u32.u64 %0, t; }" : "=r"(a) : "l"(p));
    return a;
}
__device__ __forceinline__ void cp16(uint32_t s, const void* g) {
    asm volatile("cp.async.cg.shared.global [%0], [%1], 16;" :: "r"(s), "l"(g));
}
__device__ __forceinline__ void cp_commit() {
    asm volatile("cp.async.commit_group;" ::: "memory");
}
__device__ __forceinline__ void cp_wait0() {
    asm volatile("cp.async.wait_group 0;" ::: "memory");
}
__device__ __forceinline__ void cp_wait1() {
    asm volatile("cp.async.wait_group 1;" ::: "memory");
}
#define LDSM4(r0, r1, r2, r3, a) \
    asm volatile("ldmatrix.sync.aligned.m8n8.x4.shared.b16 {%0,%1,%2,%3}, [%4];" \
                 : "=r"(r0), "=r"(r1), "=r"(r2), "=r"(r3) : "r"(a))
#define LDSM4T(r0, r1, r2, r3, a) \
    asm volatile("ldmatrix.sync.aligned.m8n8.x4.trans.shared.b16 {%0,%1,%2,%3}, [%4];" \
                 : "=r"(r0), "=r"(r1), "=r"(r2), "=r"(r3) : "r"(a))

__device__ __forceinline__ void mma16816(float* d, const uint32_t* a, uint32_t b0, uint32_t b1) {
    asm volatile(
        "mma.sync.aligned.m16n8k16.row.col.f32.f16.f16.f32 "
        "{%0,%1,%2,%3}, {%4,%5,%6,%7}, {%8,%9}, {%0,%1,%2,%3};"
        : "+f"(d[0]), "+f"(d[1]), "+f"(d[2]), "+f"(d[3])
        : "r"(a[0]), "r"(a[1]), "r"(a[2]), "r"(a[3]), "r"(b0), "r"(b1));
}

__device__ __forceinline__ uint32_t pk2(float a, float b) {
    __half2 t;
    t.x = __float2half_rn(a);
    t.y = __float2half_rn(b);
    return *(uint32_t*)&t;
}

// ---------------- RMSNorm -> fp16 ----------------
__global__ __launch_bounds__(256) void rmsnorm_kernel(
    const float* __restrict__ x, const float* __restrict__ gamma,
    __half* __restrict__ xh) {
    const int row = blockIdx.x;
    const float4* xr = (const float4*)(x + (size_t)row * HIDDEN);
    const float4* g4 = (const float4*)gamma;

    float ss = 0.f;
    float4 v[4];
#pragma unroll
    for (int i = 0; i < 4; i++) {
        v[i] = xr[threadIdx.x + 256 * i];
        ss += v[i].x * v[i].x + v[i].y * v[i].y + v[i].z * v[i].z + v[i].w * v[i].w;
    }
#pragma unroll
    for (int o = 16; o > 0; o >>= 1) ss += __shfl_xor_sync(~0u, ss, o);
    __shared__ float sred[8];
    if ((threadIdx.x & 31) == 0) sred[threadIdx.x >> 5] = ss;
    __syncthreads();
    float tot = 0.f;
#pragma unroll
    for (int i = 0; i < 8; i++) tot += sred[i];

    const float inv = rsqrtf(tot / (float)HIDDEN + 1e-5f);
    size_t rb = (size_t)row * HIDDEN;
#pragma unroll
    for (int i = 0; i < 4; i++) {
        float4 g = g4[threadIdx.x + 256 * i];
        size_t e = rb + (size_t)(threadIdx.x + 256 * i) * 4;
        __half2 h01, h23;
        h01.x = __float2half_rn(v[i].x * inv * g.x);
        h01.y = __float2half_rn(v[i].y * inv * g.y);
        h23.x = __float2half_rn(v[i].z * inv * g.z);
        h23.y = __float2half_rn(v[i].w * inv * g.w);
        *(__half2*)(xh + e) = h01;
        *(__half2*)(xh + e + 2) = h23;
    }
}

// ---------------- weight transpose + convert: W[K,N] -> T[N,K] fp16 ----------------
__global__ __launch_bounds__(256) void tconv_kernel(
    const float* __restrict__ W, __half* __restrict__ Th, int K, int N) {
    __shared__ __half sh[64][68];
    const int k0 = blockIdx.x * 64, n0 = blockIdx.y * 64;
    const int tid = threadIdx.x;

    for (int i = tid; i < 64 * 16; i += 256) {
        int r = i >> 4;
        int c4 = (i & 15) << 2;
        float4 w = *(const float4*)&W[(size_t)(k0 + r) * N + n0 + c4];
        sh[c4 + 0][r] = __float2half_rn(w.x);
        sh[c4 + 1][r] = __float2half_rn(w.y);
        sh[c4 + 2][r] = __float2half_rn(w.z);
        sh[c4 + 3][r] = __float2half_rn(w.w);
    }
    __syncthreads();
    for (int i = tid; i < 64 * 16; i += 256) {
        int n = i >> 4, kk4 = (i & 15) << 2;
        size_t off = (size_t)(n0 + n) * K + k0 + kk4;
        __half2 a, b;
        a.x = sh[n][kk4]; a.y = sh[n][kk4 + 1];
        b.x = sh[n][kk4 + 2]; b.y = sh[n][kk4 + 3];
        *(__half2*)(Th + off) = a;
        *(__half2*)(Th + off + 2) = b;
    }
}

// ---------------- mma.sync GEMM: C = A(fp16) @ T(fp16)^T (+R) ----------------
// Tile 128x128, BK=64; smem/buffer 32KB (A 16K | B 16K); double-buffered; 2 CTAs/SM.
#define GEMM_SMEM (2 * 32768)

__device__ __forceinline__ void load_sub(uint32_t sdst, const __half* src,
                                         int rbase, int K, int k0, int tid) {
#pragma unroll
    for (int p = 0; p < 4; p++) {
        int u = tid + (p << 8);
        int r = u >> 3, c16 = u & 7;
        const char* g = (const char*)(src + (size_t)(rbase + r) * K + k0) + (c16 << 4);
        cp16(sdst + r * 128 + ((c16 ^ (r & 7)) << 4), g);
    }
}

__global__ __launch_bounds__(256, 2) void gemm_mma(
    const __half* __restrict__ Ah, const __half* __restrict__ Bh,
    const float* __restrict__ R, float* __restrict__ C, int M, int N, int K) {
    extern __shared__ char smraw[];
    const uint32_t sbase = smem_u32(smraw);
    const int tid = threadIdx.x;
    const int lane = tid & 31, wid = tid >> 5;
    const int row0 = blockIdx.y * 128, col0 = blockIdx.x * 128;
    const int wm = (wid & 1) * 64, wn = (wid >> 1) * 32;

    float acc[4][4][4];
#pragma unroll
    for (int i = 0; i < 4; i++)
#pragma unroll
        for (int j = 0; j < 4; j++)
#pragma unroll
            for (int r = 0; r < 4; r++) acc[i][j][r] = 0.f;

    const int NC = K >> 6;

    load_sub(sbase,         Ah, row0, K, 0, tid);
    load_sub(sbase + 16384, Bh, col0, K, 0, tid);
    cp_commit();

    const int a_r = lane & 15;
    const int a_ch = lane >> 4;
    const int b_n = ((lane >> 4) << 3) + (lane & 7);
    const int b_kh = (lane >> 3) & 1;

    for (int c = 0; c < NC; c++) {
        const int buf = c & 1;
        if (c + 1 < NC) {
            const uint32_t nb = sbase + (buf ^ 1) * 32768;
            const int k0 = (c + 1) << 6;
            load_sub(nb,         Ah, row0, K, k0, tid);
            load_sub(nb + 16384, Bh, col0, K, k0, tid);
            cp_commit();
            cp_wait1();
        } else {
            cp_wait0();
        }
        __syncthreads();

        const uint32_t sb = sbase + buf * 32768;
#pragma unroll
        for (int ks = 0; ks < 4; ks++) {
            uint32_t aH[4][4], bH[2][4];
#pragma unroll
            for (int i = 0; i < 4; i++) {
                int r = wm + i * 16 + a_r;
                uint32_t cl = (uint32_t)((ks * 2 + a_ch) ^ (r & 7)) << 4;
                LDSM4(aH[i][0], aH[i][1], aH[i][2], aH[i][3], sb + r * 128 + cl);
            }
#pragma unroll
            for (int j = 0; j < 2; j++) {
                int r = wn + j * 16 + b_n;
                uint32_t cl = (uint32_t)((ks * 2 + b_kh) ^ (r & 7)) << 4;
                LDSM4(bH[j][0], bH[j][1], bH[j][2], bH[j][3], sb + 16384 + r * 128 + cl);
            }
#pragma unroll
            for (int i = 0; i < 4; i++) {
#pragma unroll
                for (int jn = 0; jn < 4; jn++) {
                    mma16816(acc[i][jn], aH[i],
                             bH[jn >> 1][(jn & 1) * 2], bH[jn >> 1][(jn & 1) * 2 + 1]);
                }
            }
        }
        __syncthreads();
    }

    const int mrow = lane >> 2, ncol = (lane & 3) * 2;
#pragma unroll
    for (int i = 0; i < 4; i++) {
        int gr = row0 + wm + i * 16 + mrow;
#pragma unroll
        for (int jn = 0; jn < 4; jn++) {
            int gc = col0 + wn + jn * 8 + ncol;
            float2 v0 = make_float2(acc[i][jn][0], acc[i][jn][1]);
            float2 v1 = make_float2(acc[i][jn][2], acc[i][jn][3]);
            if (R) {
                float2 r0 = *(const float2*)&R[(size_t)gr * N + gc];
                float2 r1 = *(const float2*)&R[(size_t)(gr + 8) * N + gc];
                v0.x += r0.x; v0.y += r0.y;
                v1.x += r1.x; v1.y += r1.y;
            }
            *(float2*)&C[(size_t)gr * N + gc] = v0;
            *(float2*)&C[(size_t)(gr + 8) * N + gc] = v1;
        }
    }
}

// ---------------- RoPE tables ----------------
__global__ void rope_table_kernel(float* __restrict__ cosT, float* __restrict__ sinT) {
    int idx = blockIdx.x * blockDim.x + threadIdx.x;
    if (idx >= SEQ * 64) return;
    int s = idx >> 6, i = idx & 63;
    double ang = (double)s * pow(10000.0, -(double)i / 64.0);
    double sn, cs;
    sincos(ang, &sn, &cs);
    cosT[idx] = (float)cs;
    sinT[idx] = (float)sn;
}

// ---------------- RoPE + transpose head-major -> fp16 ----------------
__global__ __launch_bounds__(256) void rope_conv_kernel(
    const float* __restrict__ src, __half* __restrict__ dh, int nheads, long total) {
    long idx = (long)blockIdx.x * blockDim.x + threadIdx.x;
    if (idx >= total) return;
    int i = (int)(idx & 63);
    long t = idx >> 6;
    int s = (int)(t & (SEQ - 1));
    t >>= 11;
    int h = (int)(t % nheads);
    int b = (int)(t / nheads);
    const float* sp = src + ((size_t)b * SEQ + s) * (size_t)(nheads * HD) + (size_t)h * HD;
    float a = sp[i], bb = sp[i + 64];
    float c = g_cos[s * 64 + i], sn = g_sin[s * 64 + i];
    size_t d = (((size_t)b * nheads + h) * SEQ + s) * HD;
    dh[d + i] = __float2half_rn(a * c - bb * sn);
    dh[d + i + 64] = __float2half_rn(bb * c + a * sn);
}

// ---------------- V transpose head-major -> fp16 ----------------
__global__ __launch_bounds__(256) void vconv_kernel(
    const float* __restrict__ src, __half* __restrict__ dh, long total) {
    long idx = (long)blockIdx.x * blockDim.x + threadIdx.x;
    if (idx >= total) return;
    int i = (int)(idx & 127);
    long t = idx >> 7;
    int s = (int)(t & (SEQ - 1));
    t >>= 11;
    int h = (int)(t % HKV);
    int b = (int)(t / HKV);
    float v = src[((size_t)b * SEQ + s) * NKV + (size_t)h * HD + i];
    dh[(((size_t)b * HKV + h) * SEQ + s) * HD + i] = __float2half_rn(v);
}

// ---------------- attention via mma.sync (fp16) ----------------
// grid (SEQ/128, HQ, B), 256 threads. smem: Q 32K | 2x{K 16K|V 16K} = 96KB
#define AT_SMEM (98304)

__global__ __launch_bounds__(256) void attn_mma(
    const __half* __restrict__ Qh, const __half* __restrict__ Kh,
    const __half* __restrict__ Vh, __half* __restrict__ Oh) {
    extern __shared__ char smraw[];
    const uint32_t S0 = smem_u32(smraw);
    const int tid = threadIdx.x;
    const int lane = tid & 31, wid = tid >> 5;
    const int qt = blockIdx.x, h = blockIdx.y, b = blockIdx.z;
    const int g = h >> 2;
    const int q0 = qt * 128;
    const int m0 = wid * 16;

    // ---- load Q into swizzled smem (256B rows) ----
    {
        const char* qb = (const char*)(Qh + (((size_t)b * HQ + h) * SEQ + q0) * HD);
#pragma unroll
        for (int p = 0; p < 8; p++) {
            int u = tid + (p << 8);
            int r = u >> 4, c = u & 15;
            cp16(S0 + r * 256 + (uint32_t)((c ^ (r & 7)) << 4), qb + r * 256 + c * 16);
        }
    }

    const size_t kvhead = ((size_t)b * HKV + g) * SEQ;
    const int kt_lo = max(0, q0 - WINDOW + 1) >> 6;
    const int kt_hi = (q0 + 127) >> 6;

    // prologue KV load: K tile 64r x 256B (1024 cp16) + V tile same -> p<4, r=u>>4 in [0,63]
    {
        const size_t kb = (kvhead + (size_t)kt_lo * 64) * HD;
        uint32_t B0 = S0 + 32768;
#pragma unroll
        for (int p = 0; p < 4; p++) {
            int u = tid + (p << 8);
            int r = u >> 4, c = u & 15;
            uint32_t off = r * 256 + (uint32_t)((c ^ (r & 7)) << 4);
            size_t go = (size_t)r * 256 + c * 16;
            cp16(B0 + off, (const char*)(Kh + kb) + go);
            cp16(B0 + 16384 + off, (const char*)(Vh + kb) + go);
        }
    }
    cp_commit();

    float acc[16][4];
#pragma unroll
    for (int i = 0; i < 16; i++)
#pragma unroll
        for (int j = 0; j < 4; j++) acc[i][j] = 0.f;
    float m_run0 = NEG_INF_F, m_run1 = NEG_INF_F, l_run0 = 0.f, l_run1 = 0.f;

    const int r0g = q0 + m0 + (lane >> 2);
    const int r1g = r0g + 8;
    const float ez = 2.0f * 0.08838834764831845f / 50.0f;

    const int a_r = lane & 15;
    const int a_ch = lane >> 4;
    const int sb_r = (lane & 7) + ((lane & 16) >> 1);
    const int sb_c = (lane >> 3) & 1;
    const int pv_r = (lane & 7) + (lane & 8);
    const int pv_c = (lane & 16) >> 4;

    for (int kt = kt_lo; kt <= kt_hi; kt++) {
        const int buf = (kt - kt_lo) & 1;
        if (kt < kt_hi) {
            const size_t kb = (kvhead + (size_t)(kt + 1) * 64) * HD;
            uint32_t NB = S0 + 32768 + (buf ^ 1) * 32768;
#pragma unroll
            for (int p = 0; p < 4; p++) {
                int u = tid + (p << 8);
                int r = u >> 4, c = u & 15;
                uint32_t off = r * 256 + (uint32_t)((c ^ (r & 7)) << 4);
                size_t go = (size_t)r * 256 + c * 16;
                cp16(NB + off, (const char*)(Kh + kb) + go);
                cp16(NB + 16384 + off, (const char*)(Vh + kb) + go);
            }
            cp_commit();
            cp_wait1();
        } else {
            cp_wait0();
        }
        __syncthreads();

        const uint32_t KB = S0 + 32768 + buf * 32768;

        // ---- scores S = Q K^T ----
        float S[8][4];
#pragma unroll
        for (int i = 0; i < 8; i++)
#pragma unroll
            for (int j = 0; j < 4; j++) S[i][j] = 0.f;

#pragma unroll
        for (int kc = 0; kc < 8; kc++) {
            uint32_t aH[4];
            {
                int r = m0 + a_r;
                uint32_t cl = (uint32_t)((2 * kc + a_ch) ^ (r & 7)) << 4;
                LDSM4(aH[0], aH[1], aH[2], aH[3], S0 + r * 256 + cl);
            }
#pragma unroll
            for (int np = 0; np < 4; np++) {
                int rr = np * 16 + sb_r;
                uint32_t cl = (uint32_t)((2 * kc + sb_c) ^ (rr & 7)) << 4;
                uint32_t bh0, bh1, bh2, bh3;
                LDSM4(bh0, bh1, bh2, bh3, KB + rr * 256 + cl);
                mma16816(S[2 * np], aH, bh0, bh1);
                mma16816(S[2 * np + 1], aH, bh2, bh3);
            }
        }

        // ---- tanh cap + mask + online softmax ----
        const int k0g = kt * 64;
        float mx0 = NEG_INF_F, mx1 = NEG_INF_F;
#pragma unroll
        for (int a = 0; a < 8; a++) {
            int cb = k0g + 8 * a + ((lane & 3) << 1);
            float t0 = __expf(ez * S[a][0]);
            float t1 = __expf(ez * S[a][1]);
            float t2 = __expf(ez * S[a][2]);
            float t3 = __expf(ez * S[a][3]);
            float v0 = 50.f * (1.f - __fdividef(2.f, t0 + 1.f));
            float v1 = 50.f * (1.f - __fdividef(2.f, t1 + 1.f));
            float v2 = 50.f * (1.f - __fdividef(2.f, t2 + 1.f));
            float v3 = 50.f * (1.f - __fdividef(2.f, t3 + 1.f));
            bool m00 = (cb <= r0g) && (cb > r0g - WINDOW);
            bool m01 = (cb + 1 <= r0g) && (cb + 1 > r0g - WINDOW);
            bool m10 = (cb <= r1g) && (cb > r1g - WINDOW);
            bool m11 = (cb + 1 <= r1g) && (cb + 1 > r1g - WINDOW);
            S[a][0] = m00 ? v0 : NEG_INF_F;
            S[a][1] = m01 ? v1 : NEG_INF_F;
            S[a][2] = m10 ? v2 : NEG_INF_F;
            S[a][3] = m11 ? v3 : NEG_INF_F;
            mx0 = fmaxf(mx0, fmaxf(S[a][0], S[a][1]));
            mx1 = fmaxf(mx1, fmaxf(S[a][2], S[a][3]));
        }
        mx0 = fmaxf(mx0, __shfl_xor_sync(~0u, mx0, 1));
        mx0 = fmaxf(mx0, __shfl_xor_sync(~0u, mx0, 2));
        mx1 = fmaxf(mx1, __shfl_xor_sync(~0u, mx1, 1));
        mx1 = fmaxf(mx1, __shfl_xor_sync(~0u, mx1, 2));

        float mn0 = fmaxf(m_run0, mx0), mn1 = fmaxf(m_run1, mx1);
        float cor0 = __expf(m_run0 - mn0), cor1 = __expf(m_run1 - mn1);
        float sum0 = 0.f, sum1 = 0.f;
#pragma unroll
        for (int a = 0; a < 8; a++) {
            float p0 = (S[a][0] > -1e29f) ? __expf(S[a][0] - mn0) : 0.f;
            float p1 = (S[a][1] > -1e29f) ? __expf(S[a][1] - mn0) : 0.f;
            float p2 = (S[a][2] > -1e29f) ? __expf(S[a][2] - mn1) : 0.f;
            float p3 = (S[a][3] > -1e29f) ? __expf(S[a][3] - mn1) : 0.f;
            S[a][0] = p0; S[a][1] = p1; S[a][2] = p2; S[a][3] = p3;
            sum0 += p0 + p1;
            sum1 += p2 + p3;
        }
        sum0 += __shfl_xor_sync(~0u, sum0, 1);
        sum0 += __shfl_xor_sync(~0u, sum0, 2);
        sum1 += __shfl_xor_sync(~0u, sum1, 1);
        sum1 += __shfl_xor_sync(~0u, sum1, 2);
        l_run0 = l_run0 * cor0 + sum0;
        l_run1 = l_run1 * cor1 + sum1;
        m_run0 = mn0;
        m_run1 = mn1;
#pragma unroll
        for (int i = 0; i < 16; i++) {
            acc[i][0] *= cor0; acc[i][1] *= cor0;
            acc[i][2] *= cor1; acc[i][3] *= cor1;
        }

        // ---- pack P (fp16) ----
        uint32_t pH[4][4];
#pragma unroll
        for (int j = 0; j < 4; j++) {
#pragma unroll
            for (int e = 0; e < 2; e++) {
                int a = 2 * j + e;
                pH[j][0 + 2 * e] = pk2(S[a][0], S[a][1]);
                pH[j][1 + 2 * e] = pk2(S[a][2], S[a][3]);
            }
        }

        // ---- O += P V, V via ldmatrix.trans ----
        const uint32_t VB = KB + 16384;
#pragma unroll
        for (int j = 0; j < 4; j++) {
            int kr = j * 16 + pv_r;
#pragma unroll
            for (int dp = 0; dp < 8; dp++) {
                uint32_t cch = (uint32_t)(2 * dp + pv_c);
                uint32_t addr = VB + kr * 256 + (((cch ^ (kr & 7))) << 4);
                uint32_t bh0, bh1, bh2, bh3;
                LDSM4T(bh0, bh1, bh2, bh3, addr);
                mma16816(acc[2 * dp], pH[j], bh0, bh1);
                mma16816(acc[2 * dp + 1], pH[j], bh2, bh3);
            }
        }
        __syncthreads();
    }

    // ---- epilogue: normalize -> fp16, layout [b*S+s][h*128+d] ----
    const float inv0 = 1.f / l_run0, inv1 = 1.f / l_run1;
    const size_t gr0 = (size_t)b * SEQ + q0 + m0 + (lane >> 2);
    const size_t gr1 = gr0 + 8;
    const int colb = h * HD + ((lane & 3) << 1);
#pragma unroll
    for (int nd = 0; nd < 16; nd++) {
        int col = colb + nd * 8;
        *(uint32_t*)(Oh + gr0 * NQ + col) = pk2(acc[nd][0] * inv0, acc[nd][1] * inv0);
        *(uint32_t*)(Oh + gr1 * NQ + col) = pk2(acc[nd][2] * inv1, acc[nd][3] * inv1);
    }
}

// ---------------- launch ----------------
extern "C" void kernel_launch(void* const* d_in, const int* in_sizes, int n_in,
                              void* d_out, int out_size) {
    const float* x = (const float*)d_in[0];
    const float* gamma = (const float*)d_in[1];
    const float* Wq = (const float*)d_in[2];
    const float* Wk = (const float*)d_in[3];
    const float* Wv = (const float*)d_in[4];
    const float* Wo = (const float*)d_in[5];
    float* out = (float*)d_out;

    __half *xnh, *wq, *wk, *wv, *wo, *ath, *qh, *kh, *vh;
    float *q, *k, *v, *cosT, *sinT;
    cudaGetSymbolAddress((void**)&xnh, g_xn_h);
    cudaGetSymbolAddress((void**)&wq, g_wqT);
    cudaGetSymbolAddress((void**)&wk, g_wkT);
    cudaGetSymbolAddress((void**)&wv, g_wvT);
    cudaGetSymbolAddress((void**)&wo, g_woT);
    cudaGetSymbolAddress((void**)&ath, g_at_h);
    cudaGetSymbolAddress((void**)&qh, g_qh);
    cudaGetSymbolAddress((void**)&kh, g_kh);
    cudaGetSymbolAddress((void**)&vh, g_vh);
    cudaGetSymbolAddress((void**)&q, g_q);
    cudaGetSymbolAddress((void**)&k, g_k);
    cudaGetSymbolAddress((void**)&v, g_v);
    cudaGetSymbolAddress((void**)&cosT, g_cos);
    cudaGetSymbolAddress((void**)&sinT, g_sin);

    cudaFuncSetAttribute(gemm_mma, cudaFuncAttributeMaxDynamicSharedMemorySize, GEMM_SMEM);
    cudaFuncSetAttribute(attn_mma, cudaFuncAttributeMaxDynamicSharedMemorySize, AT_SMEM);

    // launches 1-4: weight convert+transpose
    {
        dim3 gq(HIDDEN / 64, NQ / 64);
        tconv_kernel<<<gq, 256>>>(Wq, wq, HIDDEN, NQ);
        dim3 gk(HIDDEN / 64, NKV / 64);
        tconv_kernel<<<gk, 256>>>(Wk, wk, HIDDEN, NKV);
        tconv_kernel<<<gk, 256>>>(Wv, wv, HIDDEN, NKV);
        dim3 go(NQ / 64, HIDDEN / 64);
        tconv_kernel<<<go, 256>>>(Wo, wo, NQ, HIDDEN);
    }

    // launch 5: RMSNorm
    rmsnorm_kernel<<<MROWS, 256>>>(x, gamma, xnh);

    // launch 6: Wq GEMM  (ncu-profiled launch: -s 5 -c 1)
    {
        dim3 gq(NQ / 128, MROWS / 128);
        gemm_mma<<<gq, 256, GEMM_SMEM>>>(xnh, wq, (const float*)0, q, MROWS, NQ, HIDDEN);
    }

    // launch 7: RoPE tables
    rope_table_kernel<<<(SEQ * 64 + 255) / 256, 256>>>(cosT, sinT);

    // launches 8-9: Wk, Wv GEMMs
    {
        dim3 gk(NKV / 128, MROWS / 128);
        gemm_mma<<<gk, 256, GEMM_SMEM>>>(xnh, wk, (const float*)0, k, MROWS, NKV, HIDDEN);
        gemm_mma<<<gk, 256, GEMM_SMEM>>>(xnh, wv, (const float*)0, v, MROWS, NKV, HIDDEN);
    }

    // launches 10-12: RoPE/transpose + convert
    {
        long tq = (long)BATCH * HQ * SEQ * 64;
        rope_conv_kernel<<<(int)((tq + 255) / 256), 256>>>(q, qh, HQ, tq);
        long tk = (long)BATCH * HKV * SEQ * 64;
        rope_conv_kernel<<<(int)((tk + 255) / 256), 256>>>(k, kh, HKV, tk);
        long tv = (long)BATCH * HKV * SEQ * 128;
        vconv_kernel<<<(int)((tv + 255) / 256), 256>>>(v, vh, tv);
    }

    // launch 13: attention
    {
        dim3 ga(SEQ / 128, HQ, BATCH);
        attn_mma<<<ga, 256, AT_SMEM>>>(qh, kh, vh, ath);
    }

    // launch 14: output projection + residual
    {
        dim3 go(HIDDEN / 128, MROWS / 128);
        gemm_mma<<<go, 256, GEMM_SMEM>>>(ath, wo, x, out, MROWS, HIDDEN, NQ);
    }
}

// round 9
// speedup vs baseline: 13.0575x; 1.3270x over previous
#include <cuda_runtime.h>
#include <cuda_fp16.h>
#include <math.h>
#include <stdint.h>

#define SEQ 2048
#define BATCH 2
#define HIDDEN 4096
#define HD 128
#define HQ 32
#define HKV 8
#define WINDOW 1024
#define NEG_INF_F (-1e30f)
#define MROWS (BATCH * SEQ) /* 4096 */
#define NQ (HQ * HD)        /* 4096 */
#define NKV (HKV * HD)      /* 1024 */

// ---------------- scratch (static device arrays; no allocations) ----------------
__device__ __half g_xn_h[(size_t)MROWS * HIDDEN];
__device__ __half g_wqT[(size_t)NQ * HIDDEN];
__device__ __half g_wkT[(size_t)NKV * HIDDEN];
__device__ __half g_wvT[(size_t)NKV * HIDDEN];
__device__ __half g_woT[(size_t)HIDDEN * NQ];
// head-major fp16 for attention
__device__ __half g_qh[(size_t)BATCH * HQ * SEQ * HD];
__device__ __half g_kh[(size_t)BATCH * HKV * SEQ * HD];
__device__ __half g_vh[(size_t)BATCH * HKV * SEQ * HD];
__device__ __half g_at_h[(size_t)MROWS * NQ];
__device__ float g_cos[SEQ * 64];
__device__ float g_sin[SEQ * 64];

// ---------------- PTX helpers (baseline sm_80+ ISA only) ----------------
__device__ __forceinline__ uint32_t smem_u32(const void* p) {
    uint32_t a;
    asm("{ .reg .u64 t; cvta.to.shared.u64 t, %1; cvt.u32.u64 %0, t; }" : "=r"(a) : "l"(p));
    return a;
}
__device__ __forceinline__ void cp16(uint32_t s, const void* g) {
    asm volatile("cp.async.cg.shared.global [%0], [%1], 16;" :: "r"(s), "l"(g));
}
__device__ __forceinline__ void cp_commit() {
    asm volatile("cp.async.commit_group;" ::: "memory");
}
__device__ __forceinline__ void cp_wait0() {
    asm volatile("cp.async.wait_group 0;" ::: "memory");
}
__device__ __forceinline__ void cp_wait1() {
    asm volatile("cp.async.wait_group 1;" ::: "memory");
}
#define LDSM4(r0, r1, r2, r3, a) \
    asm volatile("ldmatrix.sync.aligned.m8n8.x4.shared.b16 {%0,%1,%2,%3}, [%4];" \
                 : "=r"(r0), "=r"(r1), "=r"(r2), "=r"(r3) : "r"(a))
#define LDSM4T(r0, r1, r2, r3, a) \
    asm volatile("ldmatrix.sync.aligned.m8n8.x4.trans.shared.b16 {%0,%1,%2,%3}, [%4];" \
                 : "=r"(r0), "=r"(r1), "=r"(r2), "=r"(r3) : "r"(a))

__device__ __forceinline__ void mma16816(float* d, const uint32_t* a, uint32_t b0, uint32_t b1) {
    asm volatile(
        "mma.sync.aligned.m16n8k16.row.col.f32.f16.f16.f32 "
        "{%0,%1,%2,%3}, {%4,%5,%6,%7}, {%8,%9}, {%0,%1,%2,%3};"
        : "+f"(d[0]), "+f"(d[1]), "+f"(d[2]), "+f"(d[3])
        : "r"(a[0]), "r"(a[1]), "r"(a[2]), "r"(a[3]), "r"(b0), "r"(b1));
}

__device__ __forceinline__ uint32_t pk2(float a, float b) {
    __half2 t;
    t.x = __float2half_rn(a);
    t.y = __float2half_rn(b);
    return *(uint32_t*)&t;
}

// ---------------- RMSNorm -> fp16 ----------------
__global__ __launch_bounds__(256) void rmsnorm_kernel(
    const float* __restrict__ x, const float* __restrict__ gamma,
    __half* __restrict__ xh) {
    const int row = blockIdx.x;
    const float4* xr = (const float4*)(x + (size_t)row * HIDDEN);
    const float4* g4 = (const float4*)gamma;

    float ss = 0.f;
    float4 v[4];
#pragma unroll
    for (int i = 0; i < 4; i++) {
        v[i] = xr[threadIdx.x + 256 * i];
        ss += v[i].x * v[i].x + v[i].y * v[i].y + v[i].z * v[i].z + v[i].w * v[i].w;
    }
#pragma unroll
    for (int o = 16; o > 0; o >>= 1) ss += __shfl_xor_sync(~0u, ss, o);
    __shared__ float sred[8];
    if ((threadIdx.x & 31) == 0) sred[threadIdx.x >> 5] = ss;
    __syncthreads();
    float tot = 0.f;
#pragma unroll
    for (int i = 0; i < 8; i++) tot += sred[i];

    const float inv = rsqrtf(tot / (float)HIDDEN + 1e-5f);
    size_t rb = (size_t)row * HIDDEN;
#pragma unroll
    for (int i = 0; i < 4; i++) {
        float4 g = g4[threadIdx.x + 256 * i];
        size_t e = rb + (size_t)(threadIdx.x + 256 * i) * 4;
        __half2 h01, h23;
        h01.x = __float2half_rn(v[i].x * inv * g.x);
        h01.y = __float2half_rn(v[i].y * inv * g.y);
        h23.x = __float2half_rn(v[i].z * inv * g.z);
        h23.y = __float2half_rn(v[i].w * inv * g.w);
        *(__half2*)(xh + e) = h01;
        *(__half2*)(xh + e + 2) = h23;
    }
}

// ---------------- weight transpose + convert: W[K,N] -> T[N,K] fp16 ----------------
__global__ __launch_bounds__(256) void tconv_kernel(
    const float* __restrict__ W, __half* __restrict__ Th, int K, int N) {
    __shared__ __half sh[64][68];
    const int k0 = blockIdx.x * 64, n0 = blockIdx.y * 64;
    const int tid = threadIdx.x;

    for (int i = tid; i < 64 * 16; i += 256) {
        int r = i >> 4;
        int c4 = (i & 15) << 2;
        float4 w = *(const float4*)&W[(size_t)(k0 + r) * N + n0 + c4];
        sh[c4 + 0][r] = __float2half_rn(w.x);
        sh[c4 + 1][r] = __float2half_rn(w.y);
        sh[c4 + 2][r] = __float2half_rn(w.z);
        sh[c4 + 3][r] = __float2half_rn(w.w);
    }
    __syncthreads();
    for (int i = tid; i < 64 * 16; i += 256) {
        int n = i >> 4, kk4 = (i & 15) << 2;
        size_t off = (size_t)(n0 + n) * K + k0 + kk4;
        __half2 a, b;
        a.x = sh[n][kk4]; a.y = sh[n][kk4 + 1];
        b.x = sh[n][kk4 + 2]; b.y = sh[n][kk4 + 3];
        *(__half2*)(Th + off) = a;
        *(__half2*)(Th + off + 2) = b;
    }
}

// ---------------- RoPE tables ----------------
__global__ void rope_table_kernel(float* __restrict__ cosT, float* __restrict__ sinT) {
    int idx = blockIdx.x * blockDim.x + threadIdx.x;
    if (idx >= SEQ * 64) return;
    int s = idx >> 6, i = idx & 63;
    double ang = (double)s * pow(10000.0, -(double)i / 64.0);
    double sn, cs;
    sincos(ang, &sn, &cs);
    cosT[idx] = (float)cs;
    sinT[idx] = (float)sn;
}

// ---------------- mma.sync GEMM with fused epilogues ----------------
// mode 0: C fp32 (+R residual)
// mode 1: RoPE + head-major fp16 -> H   (N tile 128 == one head)
// mode 2: head-major fp16 -> H (no rope)
#define GEMM_SMEM (2 * 32768)

__device__ __forceinline__ void load_sub(uint32_t sdst, const __half* src,
                                         int rbase, int K, int k0, int tid) {
#pragma unroll
    for (int p = 0; p < 4; p++) {
        int u = tid + (p << 8);
        int r = u >> 3, c16 = u & 7;
        const char* g = (const char*)(src + (size_t)(rbase + r) * K + k0) + (c16 << 4);
        cp16(sdst + r * 128 + ((c16 ^ (r & 7)) << 4), g);
    }
}

__global__ __launch_bounds__(256, 2) void gemm_mma(
    const __half* __restrict__ Ah, const __half* __restrict__ Bh,
    const float* __restrict__ R, float* __restrict__ C,
    __half* __restrict__ H, int mode, int M, int N, int K) {
    extern __shared__ char smraw[];
    const uint32_t sbase = smem_u32(smraw);
    const int tid = threadIdx.x;
    const int lane = tid & 31, wid = tid >> 5;
    const int row0 = blockIdx.y * 128, col0 = blockIdx.x * 128;
    const int wm = (wid & 1) * 64, wn = (wid >> 1) * 32;

    float acc[4][4][4];
#pragma unroll
    for (int i = 0; i < 4; i++)
#pragma unroll
        for (int j = 0; j < 4; j++)
#pragma unroll
            for (int r = 0; r < 4; r++) acc[i][j][r] = 0.f;

    const int NC = K >> 6;

    load_sub(sbase,         Ah, row0, K, 0, tid);
    load_sub(sbase + 16384, Bh, col0, K, 0, tid);
    cp_commit();

    const int a_r = lane & 15;
    const int a_ch = lane >> 4;
    const int b_n = ((lane >> 4) << 3) + (lane & 7);
    const int b_kh = (lane >> 3) & 1;

    for (int c = 0; c < NC; c++) {
        const int buf = c & 1;
        if (c + 1 < NC) {
            const uint32_t nb = sbase + (buf ^ 1) * 32768;
            const int k0 = (c + 1) << 6;
            load_sub(nb,         Ah, row0, K, k0, tid);
            load_sub(nb + 16384, Bh, col0, K, k0, tid);
            cp_commit();
            cp_wait1();
        } else {
            cp_wait0();
        }
        __syncthreads();

        const uint32_t sb = sbase + buf * 32768;
#pragma unroll
        for (int ks = 0; ks < 4; ks++) {
            uint32_t aH[4][4], bH[2][4];
#pragma unroll
            for (int i = 0; i < 4; i++) {
                int r = wm + i * 16 + a_r;
                uint32_t cl = (uint32_t)((ks * 2 + a_ch) ^ (r & 7)) << 4;
                LDSM4(aH[i][0], aH[i][1], aH[i][2], aH[i][3], sb + r * 128 + cl);
            }
#pragma unroll
            for (int j = 0; j < 2; j++) {
                int r = wn + j * 16 + b_n;
                uint32_t cl = (uint32_t)((ks * 2 + b_kh) ^ (r & 7)) << 4;
                LDSM4(bH[j][0], bH[j][1], bH[j][2], bH[j][3], sb + 16384 + r * 128 + cl);
            }
#pragma unroll
            for (int i = 0; i < 4; i++) {
#pragma unroll
                for (int jn = 0; jn < 4; jn++) {
                    mma16816(acc[i][jn], aH[i],
                             bH[jn >> 1][(jn & 1) * 2], bH[jn >> 1][(jn & 1) * 2 + 1]);
                }
            }
        }
        __syncthreads();
    }

    const int mrow = lane >> 2, ncol = (lane & 3) * 2;

    if (mode == 0) {
#pragma unroll
        for (int i = 0; i < 4; i++) {
            int gr = row0 + wm + i * 16 + mrow;
#pragma unroll
            for (int jn = 0; jn < 4; jn++) {
                int gc = col0 + wn + jn * 8 + ncol;
                float2 v0 = make_float2(acc[i][jn][0], acc[i][jn][1]);
                float2 v1 = make_float2(acc[i][jn][2], acc[i][jn][3]);
                if (R) {
                    float2 r0 = *(const float2*)&R[(size_t)gr * N + gc];
                    float2 r1 = *(const float2*)&R[(size_t)(gr + 8) * N + gc];
                    v0.x += r0.x; v0.y += r0.y;
                    v1.x += r1.x; v1.y += r1.y;
                }
                *(float2*)&C[(size_t)gr * N + gc] = v0;
                *(float2*)&C[(size_t)(gr + 8) * N + gc] = v1;
            }
        }
    } else if (mode == 2) {
        const int head = col0 >> 7;
        const int nh = N >> 7;
#pragma unroll
        for (int i = 0; i < 4; i++) {
            int gr = row0 + wm + i * 16 + mrow;
            int s0 = gr & (SEQ - 1), b0 = gr >> 11;
            int s1 = (gr + 8) & (SEQ - 1), b1 = (gr + 8) >> 11;
#pragma unroll
            for (int jn = 0; jn < 4; jn++) {
                int d = wn + jn * 8 + ncol;
                *(uint32_t*)(H + (((size_t)b0 * nh + head) * SEQ + s0) * HD + d) =
                    pk2(acc[i][jn][0], acc[i][jn][1]);
                *(uint32_t*)(H + (((size_t)b1 * nh + head) * SEQ + s1) * HD + d) =
                    pk2(acc[i][jn][2], acc[i][jn][3]);
            }
        }
    } else {
        // mode 1: stage to smem (XOR-swizzled float2), rope pairs (d, d+64), fp16 head-major
        float2* F2 = (float2*)smraw;
#pragma unroll
        for (int i = 0; i < 4; i++) {
            int rl0 = wm + i * 16 + mrow;
            int rl1 = rl0 + 8;
#pragma unroll
            for (int jn = 0; jn < 4; jn++) {
                int c2 = (wn + jn * 8 + ncol) >> 1;
                F2[rl0 * 64 + (c2 ^ (rl0 & 15))] = make_float2(acc[i][jn][0], acc[i][jn][1]);
                F2[rl1 * 64 + (c2 ^ (rl1 & 15))] = make_float2(acc[i][jn][2], acc[i][jn][3]);
            }
        }
        __syncthreads();

        const int head = col0 >> 7;
        const int nh = N >> 7;
#pragma unroll
        for (int pass = 0; pass < 16; pass++) {
            int r = pass * 8 + (tid >> 5);
            float2 t1 = F2[r * 64 + (lane ^ (r & 15))];
            float2 t2 = F2[r * 64 + ((lane + 32) ^ (r & 15))];
            int d = lane * 2;
            int grow = row0 + r;
            int s = grow & (SEQ - 1), bb = grow >> 11;
            float ca = g_cos[s * 64 + d], cb = g_cos[s * 64 + d + 1];
            float sa = g_sin[s * 64 + d], sb = g_sin[s * 64 + d + 1];
            size_t base = (((size_t)bb * nh + head) * SEQ + s) * HD;
            *(uint32_t*)(H + base + d) = pk2(t1.x * ca - t2.x * sa, t1.y * cb - t2.y * sb);
            *(uint32_t*)(H + base + d + 64) = pk2(t2.x * ca + t1.x * sa, t2.y * cb + t1.y * sb);
        }
    }
}

// ---------------- attention via mma.sync (fp16) ----------------
#define AT_SMEM (98304)

__global__ __launch_bounds__(256) void attn_mma(
    const __half* __restrict__ Qh, const __half* __restrict__ Kh,
    const __half* __restrict__ Vh, __half* __restrict__ Oh) {
    extern __shared__ char smraw[];
    const uint32_t S0 = smem_u32(smraw);
    const int tid = threadIdx.x;
    const int lane = tid & 31, wid = tid >> 5;
    const int qt = blockIdx.x, h = blockIdx.y, b = blockIdx.z;
    const int g = h >> 2;
    const int q0 = qt * 128;
    const int m0 = wid * 16;

    {
        const char* qb = (const char*)(Qh + (((size_t)b * HQ + h) * SEQ + q0) * HD);
#pragma unroll
        for (int p = 0; p < 8; p++) {
            int u = tid + (p << 8);
            int r = u >> 4, c = u & 15;
            cp16(S0 + r * 256 + (uint32_t)((c ^ (r & 7)) << 4), qb + r * 256 + c * 16);
        }
    }

    const size_t kvhead = ((size_t)b * HKV + g) * SEQ;
    const int kt_lo = max(0, q0 - WINDOW + 1) >> 6;
    const int kt_hi = (q0 + 127) >> 6;

    {
        const size_t kb = (kvhead + (size_t)kt_lo * 64) * HD;
        uint32_t B0 = S0 + 32768;
#pragma unroll
        for (int p = 0; p < 4; p++) {
            int u = tid + (p << 8);
            int r = u >> 4, c = u & 15;
            uint32_t off = r * 256 + (uint32_t)((c ^ (r & 7)) << 4);
            size_t go = (size_t)r * 256 + c * 16;
            cp16(B0 + off, (const char*)(Kh + kb) + go);
            cp16(B0 + 16384 + off, (const char*)(Vh + kb) + go);
        }
    }
    cp_commit();

    float acc[16][4];
#pragma unroll
    for (int i = 0; i < 16; i++)
#pragma unroll
        for (int j = 0; j < 4; j++) acc[i][j] = 0.f;
    float m_run0 = NEG_INF_F, m_run1 = NEG_INF_F, l_run0 = 0.f, l_run1 = 0.f;

    const int r0g = q0 + m0 + (lane >> 2);
    const int r1g = r0g + 8;
    const float ez = 2.0f * 0.08838834764831845f / 50.0f;

    const int a_r = lane & 15;
    const int a_ch = lane >> 4;
    const int sb_r = (lane & 7) + ((lane & 16) >> 1);
    const int sb_c = (lane >> 3) & 1;
    const int pv_r = (lane & 7) + (lane & 8);
    const int pv_c = (lane & 16) >> 4;

    for (int kt = kt_lo; kt <= kt_hi; kt++) {
        const int buf = (kt - kt_lo) & 1;
        if (kt < kt_hi) {
            const size_t kb = (kvhead + (size_t)(kt + 1) * 64) * HD;
            uint32_t NB = S0 + 32768 + (buf ^ 1) * 32768;
#pragma unroll
            for (int p = 0; p < 4; p++) {
                int u = tid + (p << 8);
                int r = u >> 4, c = u & 15;
                uint32_t off = r * 256 + (uint32_t)((c ^ (r & 7)) << 4);
                size_t go = (size_t)r * 256 + c * 16;
                cp16(NB + off, (const char*)(Kh + kb) + go);
                cp16(NB + 16384 + off, (const char*)(Vh + kb) + go);
            }
            cp_commit();
            cp_wait1();
        } else {
            cp_wait0();
        }
        __syncthreads();

        const uint32_t KB = S0 + 32768 + buf * 32768;

        float S[8][4];
#pragma unroll
        for (int i = 0; i < 8; i++)
#pragma unroll
            for (int j = 0; j < 4; j++) S[i][j] = 0.f;

#pragma unroll
        for (int kc = 0; kc < 8; kc++) {
            uint32_t aH[4];
            {
                int r = m0 + a_r;
                uint32_t cl = (uint32_t)((2 * kc + a_ch) ^ (r & 7)) << 4;
                LDSM4(aH[0], aH[1], aH[2], aH[3], S0 + r * 256 + cl);
            }
#pragma unroll
            for (int np = 0; np < 4; np++) {
                int rr = np * 16 + sb_r;
                uint32_t cl = (uint32_t)((2 * kc + sb_c) ^ (rr & 7)) << 4;
                uint32_t bh0, bh1, bh2, bh3;
                LDSM4(bh0, bh1, bh2, bh3, KB + rr * 256 + cl);
                mma16816(S[2 * np], aH, bh0, bh1);
                mma16816(S[2 * np + 1], aH, bh2, bh3);
            }
        }

        const int k0g = kt * 64;
        float mx0 = NEG_INF_F, mx1 = NEG_INF_F;
#pragma unroll
        for (int a = 0; a < 8; a++) {
            int cb = k0g + 8 * a + ((lane & 3) << 1);
            float t0 = __expf(ez * S[a][0]);
            float t1 = __expf(ez * S[a][1]);
            float t2 = __expf(ez * S[a][2]);
            float t3 = __expf(ez * S[a][3]);
            float v0 = 50.f * (1.f - __fdividef(2.f, t0 + 1.f));
            float v1 = 50.f * (1.f - __fdividef(2.f, t1 + 1.f));
            float v2 = 50.f * (1.f - __fdividef(2.f, t2 + 1.f));
            float v3 = 50.f * (1.f - __fdividef(2.f, t3 + 1.f));
            bool m00 = (cb <= r0g) && (cb > r0g - WINDOW);
            bool m01 = (cb + 1 <= r0g) && (cb + 1 > r0g - WINDOW);
            bool m10 = (cb <= r1g) && (cb > r1g - WINDOW);
            bool m11 = (cb + 1 <= r1g) && (cb + 1 > r1g - WINDOW);
            S[a][0] = m00 ? v0 : NEG_INF_F;
            S[a][1] = m01 ? v1 : NEG_INF_F;
            S[a][2] = m10 ? v2 : NEG_INF_F;
            S[a][3] = m11 ? v3 : NEG_INF_F;
            mx0 = fmaxf(mx0, fmaxf(S[a][0], S[a][1]));
            mx1 = fmaxf(mx1, fmaxf(S[a][2], S[a][3]));
        }
        mx0 = fmaxf(mx0, __shfl_xor_sync(~0u, mx0, 1));
        mx0 = fmaxf(mx0, __shfl_xor_sync(~0u, mx0, 2));
        mx1 = fmaxf(mx1, __shfl_xor_sync(~0u, mx1, 1));
        mx1 = fmaxf(mx1, __shfl_xor_sync(~0u, mx1, 2));

        float mn0 = fmaxf(m_run0, mx0), mn1 = fmaxf(m_run1, mx1);
        float cor0 = __expf(m_run0 - mn0), cor1 = __expf(m_run1 - mn1);
        float sum0 = 0.f, sum1 = 0.f;
#pragma unroll
        for (int a = 0; a < 8; a++) {
            float p0 = (S[a][0] > -1e29f) ? __expf(S[a][0] - mn0) : 0.f;
            float p1 = (S[a][1] > -1e29f) ? __expf(S[a][1] - mn0) : 0.f;
            float p2 = (S[a][2] > -1e29f) ? __expf(S[a][2] - mn1) : 0.f;
            float p3 = (S[a][3] > -1e29f) ? __expf(S[a][3] - mn1) : 0.f;
            S[a][0] = p0; S[a][1] = p1; S[a][2] = p2; S[a][3] = p3;
            sum0 += p0 + p1;
            sum1 += p2 + p3;
        }
        sum0 += __shfl_xor_sync(~0u, sum0, 1);
        sum0 += __shfl_xor_sync(~0u, sum0, 2);
        sum1 += __shfl_xor_sync(~0u, sum1, 1);
        sum1 += __shfl_xor_sync(~0u, sum1, 2);
        l_run0 = l_run0 * cor0 + sum0;
        l_run1 = l_run1 * cor1 + sum1;
        m_run0 = mn0;
        m_run1 = mn1;
#pragma unroll
        for (int i = 0; i < 16; i++) {
            acc[i][0] *= cor0; acc[i][1] *= cor0;
            acc[i][2] *= cor1; acc[i][3] *= cor1;
        }

        uint32_t pH[4][4];
#pragma unroll
        for (int j = 0; j < 4; j++) {
#pragma unroll
            for (int e = 0; e < 2; e++) {
                int a = 2 * j + e;
                pH[j][0 + 2 * e] = pk2(S[a][0], S[a][1]);
                pH[j][1 + 2 * e] = pk2(S[a][2], S[a][3]);
            }
        }

        const uint32_t VB = KB + 16384;
#pragma unroll
        for (int j = 0; j < 4; j++) {
            int kr = j * 16 + pv_r;
#pragma unroll
            for (int dp = 0; dp < 8; dp++) {
                uint32_t cch = (uint32_t)(2 * dp + pv_c);
                uint32_t addr = VB + kr * 256 + (((cch ^ (kr & 7))) << 4);
                uint32_t bh0, bh1, bh2, bh3;
                LDSM4T(bh0, bh1, bh2, bh3, addr);
                mma16816(acc[2 * dp], pH[j], bh0, bh1);
                mma16816(acc[2 * dp + 1], pH[j], bh2, bh3);
            }
        }
        __syncthreads();
    }

    const float inv0 = 1.f / l_run0, inv1 = 1.f / l_run1;
    const size_t gr0 = (size_t)b * SEQ + q0 + m0 + (lane >> 2);
    const size_t gr1 = gr0 + 8;
    const int colb = h * HD + ((lane & 3) << 1);
#pragma unroll
    for (int nd = 0; nd < 16; nd++) {
        int col = colb + nd * 8;
        *(uint32_t*)(Oh + gr0 * NQ + col) = pk2(acc[nd][0] * inv0, acc[nd][1] * inv0);
        *(uint32_t*)(Oh + gr1 * NQ + col) = pk2(acc[nd][2] * inv1, acc[nd][3] * inv1);
    }
}

// ---------------- launch ----------------
extern "C" void kernel_launch(void* const* d_in, const int* in_sizes, int n_in,
                              void* d_out, int out_size) {
    const float* x = (const float*)d_in[0];
    const float* gamma = (const float*)d_in[1];
    const float* Wq = (const float*)d_in[2];
    const float* Wk = (const float*)d_in[3];
    const float* Wv = (const float*)d_in[4];
    const float* Wo = (const float*)d_in[5];
    float* out = (float*)d_out;

    __half *xnh, *wq, *wk, *wv, *wo, *ath, *qh, *kh, *vh;
    float *cosT, *sinT;
    cudaGetSymbolAddress((void**)&xnh, g_xn_h);
    cudaGetSymbolAddress((void**)&wq, g_wqT);
    cudaGetSymbolAddress((void**)&wk, g_wkT);
    cudaGetSymbolAddress((void**)&wv, g_wvT);
    cudaGetSymbolAddress((void**)&wo, g_woT);
    cudaGetSymbolAddress((void**)&ath, g_at_h);
    cudaGetSymbolAddress((void**)&qh, g_qh);
    cudaGetSymbolAddress((void**)&kh, g_kh);
    cudaGetSymbolAddress((void**)&vh, g_vh);
    cudaGetSymbolAddress((void**)&cosT, g_cos);
    cudaGetSymbolAddress((void**)&sinT, g_sin);

    cudaFuncSetAttribute(gemm_mma, cudaFuncAttributeMaxDynamicSharedMemorySize, GEMM_SMEM);
    cudaFuncSetAttribute(attn_mma, cudaFuncAttributeMaxDynamicSharedMemorySize, AT_SMEM);

    // RoPE tables first (consumed by GEMM epilogues)
    rope_table_kernel<<<(SEQ * 64 + 255) / 256, 256>>>(cosT, sinT);

    // weight convert+transpose
    {
        dim3 gq(HIDDEN / 64, NQ / 64);
        tconv_kernel<<<gq, 256>>>(Wq, wq, HIDDEN, NQ);
        dim3 gk(HIDDEN / 64, NKV / 64);
        tconv_kernel<<<gk, 256>>>(Wk, wk, HIDDEN, NKV);
        tconv_kernel<<<gk, 256>>>(Wv, wv, HIDDEN, NKV);
        dim3 go(NQ / 64, HIDDEN / 64);
        tconv_kernel<<<go, 256>>>(Wo, wo, NQ, HIDDEN);
    }

    // RMSNorm
    rmsnorm_kernel<<<MROWS, 256>>>(x, gamma, xnh);

    // QKV projections with fused RoPE/transpose/convert epilogues
    {
        dim3 gq(NQ / 128, MROWS / 128);
        gemm_mma<<<gq, 256, GEMM_SMEM>>>(xnh, wq, (const float*)0, (float*)0, qh, 1,
                                         MROWS, NQ, HIDDEN);
        dim3 gk(NKV / 128, MROWS / 128);
        gemm_mma<<<gk, 256, GEMM_SMEM>>>(xnh, wk, (const float*)0, (float*)0, kh, 1,
                                         MROWS, NKV, HIDDEN);
        gemm_mma<<<gk, 256, GEMM_SMEM>>>(xnh, wv, (const float*)0, (float*)0, vh, 2,
                                         MROWS, NKV, HIDDEN);
    }

    // attention
    {
        dim3 ga(SEQ / 128, HQ, BATCH);
        attn_mma<<<ga, 256, AT_SMEM>>>(qh, kh, vh, ath);
    }

    // output projection + residual
    {
        dim3 go(HIDDEN / 128, MROWS / 128);
        gemm_mma<<<go, 256, GEMM_SMEM>>>(ath, wo, x, out, (__half*)0, 0,
                                         MROWS, HIDDEN, NQ);
    }
}